// round 2
// baseline (speedup 1.0000x reference)
#include <cuda_runtime.h>
#include <cuda_bf16.h>

// Problem constants
#define BB 2
#define SS 2048
#define EE 1024
#define HH 16
#define DD 64
#define MM (BB*SS)          // 4096 rows for all GEMMs

// Scratch (device globals; no allocation allowed)
__device__ float g_Qt[BB*HH*DD*SS];   // [bh][d][s]  (d-major for attention)
__device__ float g_Kt[BB*HH*DD*SS];   // [bh][d][s]
__device__ float g_V [BB*HH*SS*DD];   // [bh][s][d]
__device__ float g_ctx[BB*SS*EE];     // [b*s][e]

// ---------------------------------------------------------------------------
// Generic 128x128x16 SGEMM body: C[M=4096, N=1024] = A[4096,1024] @ W[:, wcol0:wcol0+1024] + bias
// mode 0 -> g_Qt (d-major), 1 -> g_Kt (d-major), 2 -> g_V (s-major), 3 -> Cout row-major
// ---------------------------------------------------------------------------
__device__ __forceinline__ void gemm_body(
    const float* __restrict__ A,
    const float* __restrict__ W, int ldw, int wcol0,
    const float* __restrict__ bias, int biasoff,
    float* __restrict__ Cout, int mode)
{
    __shared__ float As[16][132];   // [k][m], padded
    __shared__ float Bs[16][128];   // [k][n]

    const int tid = threadIdx.x;
    const int ty = tid >> 4;        // 0..15
    const int tx = tid & 15;        // 0..15
    const int m0 = blockIdx.y << 7;
    const int n0 = blockIdx.x << 7;

    float acc[8][8] = {};

    for (int kt = 0; kt < EE; kt += 16) {
        // load A tile (128 rows x 16 cols), transpose into As[k][m]
        #pragma unroll
        for (int it = 0; it < 2; ++it) {
            int f = tid + (it << 8);        // 0..511
            int r = f >> 2;                 // 0..127
            int c = (f & 3) << 2;           // 0,4,8,12
            float4 v = *(const float4*)(A + (size_t)(m0 + r) * EE + kt + c);
            As[c + 0][r] = v.x;
            As[c + 1][r] = v.y;
            As[c + 2][r] = v.z;
            As[c + 3][r] = v.w;
        }
        // load W tile (16 rows x 128 cols)
        #pragma unroll
        for (int it = 0; it < 2; ++it) {
            int f = tid + (it << 8);
            int r = f >> 5;                 // 0..15
            int c = (f & 31) << 2;          // 0..124
            *(float4*)&Bs[r][c] =
                *(const float4*)(W + (size_t)(kt + r) * ldw + wcol0 + n0 + c);
        }
        __syncthreads();

        #pragma unroll
        for (int kk = 0; kk < 16; ++kk) {
            float a[8], b[8];
            *(float4*)&a[0] = *(float4*)&As[kk][ty * 8];
            *(float4*)&a[4] = *(float4*)&As[kk][ty * 8 + 4];
            *(float4*)&b[0] = *(float4*)&Bs[kk][tx * 8];
            *(float4*)&b[4] = *(float4*)&Bs[kk][tx * 8 + 4];
            #pragma unroll
            for (int i = 0; i < 8; ++i)
                #pragma unroll
                for (int j = 0; j < 8; ++j)
                    acc[i][j] = fmaf(a[i], b[j], acc[i][j]);
        }
        __syncthreads();
    }

    // epilogue
    #pragma unroll
    for (int i = 0; i < 8; ++i) {
        int m = m0 + ty * 8 + i;
        int b = m >> 11;            // /2048
        int s = m & (SS - 1);
        #pragma unroll
        for (int j = 0; j < 8; ++j) {
            int n = n0 + tx * 8 + j;
            float val = acc[i][j] + bias[biasoff + n];
            int h = n >> 6;         // /64
            int d = n & 63;
            if (mode == 0)
                g_Qt[(size_t)(((b << 4) + h) * DD + d) * SS + s] = val;
            else if (mode == 1)
                g_Kt[(size_t)(((b << 4) + h) * DD + d) * SS + s] = val;
            else if (mode == 2)
                g_V[(size_t)(((b << 4) + h) * SS + s) * DD + d] = val;
            else
                Cout[(size_t)m * EE + n] = val;
        }
    }
}

__global__ void qkv_gemm_kernel(const float* __restrict__ q,
                                const float* __restrict__ k,
                                const float* __restrict__ v,
                                const float* __restrict__ Wqkv,
                                const float* __restrict__ bqkv)
{
    int z = blockIdx.z;
    const float* A = (z == 0) ? q : (z == 1) ? k : v;
    gemm_body(A, Wqkv, 3 * EE, z << 10, bqkv, z << 10, nullptr, z);
}

__global__ void out_gemm_kernel(const float* __restrict__ Wout,
                                const float* __restrict__ bout,
                                float* __restrict__ out)
{
    gemm_body(g_ctx, Wout, EE, 0, bout, 0, out, 3);
}

// ---------------------------------------------------------------------------
// Flash attention: Br=64 queries per block, Bc=64 key chunk, 256 threads (16x16),
// each thread owns a 4x4 microtile. Q/K read d-major from scratch (no transpose).
// Row stats reduced across the 16-lane tx group via shfl.
// ---------------------------------------------------------------------------
__global__ void attn_kernel(const int* __restrict__ mask)
{
    extern __shared__ float sm[];
    float* Qs = sm;              // [64][64]  Qs[d][i]
    float* Ks = sm + 4096;       // [64][64]  Ks[d][j]
    float* Vs = sm + 8192;       // [64][64]  Vs[j][d]
    float* Ps = sm + 12288;      // [64][64]  P tile; unioned with mask tile
    int*   Msk = (int*)Ps;

    const int bh = blockIdx.y;       // 0..31
    const int q0 = blockIdx.x << 6;  // query tile start
    const int tid = threadIdx.x;
    const int ty = tid >> 4;
    const int tx = tid & 15;
    const int i0 = ty << 2;
    const int j0 = tx << 2;

    const float* Qbase = g_Qt + (size_t)bh * DD * SS;
    const float* Kbase = g_Kt + (size_t)bh * DD * SS;
    const float* Vbase = g_V + (size_t)bh * SS * DD;

    // load Q tile (d-major -> Qs[d][i]) once
    #pragma unroll
    for (int it = 0; it < 4; ++it) {
        int idx = tid + (it << 8);      // 0..1023
        int d = idx >> 4;
        int c = (idx & 15) << 2;
        *(float4*)&Qs[d * 64 + c] = *(const float4*)(Qbase + (size_t)d * SS + q0 + c);
    }

    float mi[4], li[4], O[4][4];
    #pragma unroll
    for (int i = 0; i < 4; ++i) {
        mi[i] = -1e30f;
        li[i] = 0.f;
        #pragma unroll
        for (int j = 0; j < 4; ++j) O[i][j] = 0.f;
    }

    for (int kc = 0; kc < SS; kc += 64) {
        __syncthreads();   // previous PV reads done before overwrite
        #pragma unroll
        for (int it = 0; it < 4; ++it) {
            int idx = tid + (it << 8);
            int r = idx >> 4;
            int c = (idx & 15) << 2;
            *(float4*)&Ks[r * 64 + c] = *(const float4*)(Kbase + (size_t)r * SS + kc + c);
            *(float4*)&Vs[r * 64 + c] = *(const float4*)(Vbase + (size_t)(kc + r) * DD + c);
            *(int4*)&Msk[r * 64 + c]  = *(const int4*)(mask + (size_t)(q0 + r) * SS + kc + c);
        }
        __syncthreads();

        // S = Q @ K^T  (4x4 per thread)
        float sa[4][4] = {};
        #pragma unroll 16
        for (int d = 0; d < 64; ++d) {
            float4 qv = *(float4*)&Qs[d * 64 + i0];
            float4 kv = *(float4*)&Ks[d * 64 + j0];
            float qa[4] = {qv.x, qv.y, qv.z, qv.w};
            float ka[4] = {kv.x, kv.y, kv.z, kv.w};
            #pragma unroll
            for (int i = 0; i < 4; ++i)
                #pragma unroll
                for (int j = 0; j < 4; ++j)
                    sa[i][j] = fmaf(qa[i], ka[j], sa[i][j]);
        }

        // scale + mask + per-chunk rowmax
        float rm[4];
        #pragma unroll
        for (int i = 0; i < 4; ++i) {
            rm[i] = -1e30f;
            #pragma unroll
            for (int j = 0; j < 4; ++j) {
                float s = sa[i][j] * 0.125f;   // 1/sqrt(64)
                if (Msk[(i0 + i) * 64 + j0 + j] == 0) s = -1e30f;
                sa[i][j] = s;
                rm[i] = fmaxf(rm[i], s);
            }
            rm[i] = fmaxf(rm[i], __shfl_xor_sync(0xffffffffu, rm[i], 8));
            rm[i] = fmaxf(rm[i], __shfl_xor_sync(0xffffffffu, rm[i], 4));
            rm[i] = fmaxf(rm[i], __shfl_xor_sync(0xffffffffu, rm[i], 2));
            rm[i] = fmaxf(rm[i], __shfl_xor_sync(0xffffffffu, rm[i], 1));
        }

        // online softmax update + write P
        #pragma unroll
        for (int i = 0; i < 4; ++i) {
            float mn = fmaxf(mi[i], rm[i]);
            float alpha = __expf(mi[i] - mn);
            mi[i] = mn;
            float rs = 0.f;
            #pragma unroll
            for (int j = 0; j < 4; ++j) {
                float p = __expf(sa[i][j] - mn);
                Ps[(i0 + i) * 64 + j0 + j] = p;
                rs += p;
            }
            rs += __shfl_xor_sync(0xffffffffu, rs, 8);
            rs += __shfl_xor_sync(0xffffffffu, rs, 4);
            rs += __shfl_xor_sync(0xffffffffu, rs, 2);
            rs += __shfl_xor_sync(0xffffffffu, rs, 1);
            li[i] = li[i] * alpha + rs;
            #pragma unroll
            for (int j = 0; j < 4; ++j) O[i][j] *= alpha;
        }
        __syncwarp();   // Ps exchange is within the same warp's 16-lane groups

        // O += P @ V
        #pragma unroll 16
        for (int j = 0; j < 64; ++j) {
            float4 vv = *(float4*)&Vs[j * 64 + j0];
            float va[4] = {vv.x, vv.y, vv.z, vv.w};
            #pragma unroll
            for (int i = 0; i < 4; ++i) {
                float p = Ps[(i0 + i) * 64 + j];
                #pragma unroll
                for (int jj = 0; jj < 4; ++jj)
                    O[i][jj] = fmaf(p, va[jj], O[i][jj]);
            }
        }
    }

    // write ctx [b][s][h*64+d]
    int b = bh >> 4, h = bh & 15;
    #pragma unroll
    for (int i = 0; i < 4; ++i) {
        float inv = 1.0f / li[i];
        size_t rowoff = (size_t)((b << 11) + q0 + i0 + i) * EE + (h << 6) + j0;
        #pragma unroll
        for (int j = 0; j < 4; ++j)
            g_ctx[rowoff + j] = O[i][j] * inv;
    }
}

// ---------------------------------------------------------------------------
extern "C" void kernel_launch(void* const* d_in, const int* in_sizes, int n_in,
                              void* d_out, int out_size)
{
    const float* q    = (const float*)d_in[0];
    const float* k    = (const float*)d_in[1];
    const float* v    = (const float*)d_in[2];
    const int*   mask = (const int*)  d_in[3];
    const float* Wqkv = (const float*)d_in[4];
    const float* bqkv = (const float*)d_in[5];
    const float* Wout = (const float*)d_in[6];
    const float* bout = (const float*)d_in[7];
    float* out = (float*)d_out;

    // 1) fused QKV projection (z selects q/k/v slice of Wqkv)
    qkv_gemm_kernel<<<dim3(8, 32, 3), 256>>>(q, k, v, Wqkv, bqkv);

    // 2) flash attention (64KB dynamic smem)
    cudaFuncSetAttribute(attn_kernel, cudaFuncAttributeMaxDynamicSharedMemorySize, 65536);
    attn_kernel<<<dim3(SS / 64, BB * HH), 256, 65536>>>(mask);

    // 3) output projection
    out_gemm_kernel<<<dim3(8, 32), 256>>>(Wout, bout, out);
}

// round 4
// speedup vs baseline: 2.0139x; 2.0139x over previous
#include <cuda_runtime.h>
#include <cstdint>

// Problem constants
#define BB 2
#define SS 2048
#define EE 1024
#define HH 16
#define DD 64

// Scratch (device globals; no allocation allowed). All [bh][s][d] row-major.
__device__ float g_Q[BB*HH*SS*DD];
__device__ float g_K[BB*HH*SS*DD];
__device__ float g_V[BB*HH*SS*DD];
__device__ float g_ctx[BB*SS*EE];     // [b*s][e]

// ---------------------------------------------------------------------------
__device__ __forceinline__ uint32_t f2tf(float f){
    uint32_t r; asm("cvt.rna.tf32.f32 %0, %1;" : "=r"(r) : "f"(f)); return r;
}

// m16n8k8 tf32 mma: D = A*B + D
__device__ __forceinline__ void mma8(float c[4], const uint32_t a[4], const uint32_t b[2]){
    asm volatile(
        "mma.sync.aligned.m16n8k8.row.col.f32.tf32.tf32.f32 "
        "{%0,%1,%2,%3}, {%4,%5,%6,%7}, {%8,%9}, {%0,%1,%2,%3};"
        : "+f"(c[0]), "+f"(c[1]), "+f"(c[2]), "+f"(c[3])
        : "r"(a[0]), "r"(a[1]), "r"(a[2]), "r"(a[3]), "r"(b[0]), "r"(b[1]));
}

// ---------------------------------------------------------------------------
// tf32 mma GEMM: C[4096, *] = A[4096,1024] @ W[:, n0:n0+128] + bias
// CTA 128x128, 8 warps (4m x 2n), warp tile 32x64, k-tile 32.
// mode 0/1/2 -> g_Q/g_K/g_V as [bh][s][d]; mode 3 -> Cout row-major [m][1024].
// ---------------------------------------------------------------------------
__device__ __forceinline__ void mma_gemm_body(
    const float* __restrict__ A,
    const float* __restrict__ W, int ldw,
    const float* __restrict__ bias,
    float* __restrict__ Cout, int mode, int n0)
{
    __shared__ uint32_t As[128 * 36];   // [m][k] ld=36 (conflict-free frag reads)
    __shared__ uint32_t Bs[32 * 136];   // [k][n] ld=136

    const int tid = threadIdx.x, lane = tid & 31, wid = tid >> 5;
    const int g = lane >> 2, qp = lane & 3;
    const int m0 = blockIdx.y << 7;
    const int wm0 = (wid & 3) << 5;     // warp m offset
    const int wn0 = (wid >> 2) << 6;    // warp n offset

    float acc[2][8][4] = {};

    for (int kt = 0; kt < EE; kt += 32) {
        #pragma unroll
        for (int it = 0; it < 4; ++it) {
            int f = tid + (it << 8);
            int r = f >> 3, c = (f & 7) << 2;
            float4 v = *(const float4*)(A + (size_t)(m0 + r) * EE + kt + c);
            uint4 u = make_uint4(f2tf(v.x), f2tf(v.y), f2tf(v.z), f2tf(v.w));
            *(uint4*)&As[r * 36 + c] = u;
        }
        #pragma unroll
        for (int it = 0; it < 4; ++it) {
            int f = tid + (it << 8);
            int r = f >> 5, c = (f & 31) << 2;
            float4 v = *(const float4*)(W + (size_t)(kt + r) * ldw + n0 + c);
            uint4 u = make_uint4(f2tf(v.x), f2tf(v.y), f2tf(v.z), f2tf(v.w));
            *(uint4*)&Bs[r * 136 + c] = u;
        }
        __syncthreads();

        #pragma unroll
        for (int ks = 0; ks < 4; ++ks) {
            uint32_t a[2][4];
            #pragma unroll
            for (int mf = 0; mf < 2; ++mf) {
                int mr = wm0 + mf * 16 + g;
                a[mf][0] = As[mr * 36 + ks * 8 + qp];
                a[mf][1] = As[(mr + 8) * 36 + ks * 8 + qp];
                a[mf][2] = As[mr * 36 + ks * 8 + qp + 4];
                a[mf][3] = As[(mr + 8) * 36 + ks * 8 + qp + 4];
            }
            #pragma unroll
            for (int nf = 0; nf < 8; ++nf) {
                uint32_t b[2];
                b[0] = Bs[(ks * 8 + qp) * 136 + wn0 + nf * 8 + g];
                b[1] = Bs[(ks * 8 + qp + 4) * 136 + wn0 + nf * 8 + g];
                mma8(acc[0][nf], a[0], b);
                mma8(acc[1][nf], a[1], b);
            }
        }
        __syncthreads();
    }

    // epilogue: direct stores (32B-sector-aligned float2 groups per 4-lane row set)
    #pragma unroll
    for (int mf = 0; mf < 2; ++mf) {
        #pragma unroll
        for (int nf = 0; nf < 8; ++nf) {
            int n = n0 + wn0 + nf * 8 + 2 * qp;
            float b0 = bias[n], b1 = bias[n + 1];
            #pragma unroll
            for (int rr = 0; rr < 2; ++rr) {
                int m = m0 + wm0 + mf * 16 + g + rr * 8;
                float2 val = make_float2(acc[mf][nf][rr * 2 + 0] + b0,
                                         acc[mf][nf][rr * 2 + 1] + b1);
                if (mode < 3) {
                    int nn = n & 1023;
                    int h = nn >> 6, d = nn & 63;
                    int b = m >> 11, s = m & (SS - 1);
                    float* dst = (mode == 0) ? g_Q : (mode == 1) ? g_K : g_V;
                    *(float2*)(dst + ((size_t)((b << 4) + h) * SS + s) * DD + d) = val;
                } else {
                    *(float2*)(Cout + (size_t)m * EE + n) = val;
                }
            }
        }
    }
}

__global__ void __launch_bounds__(256, 2)
qkv_mma_kernel(const float* __restrict__ q, const float* __restrict__ k,
               const float* __restrict__ v, const float* __restrict__ Wqkv,
               const float* __restrict__ bqkv)
{
    int n0 = blockIdx.x << 7;       // 0..2944 across Q|K|V sections
    int sec = n0 >> 10;
    const float* A = (sec == 0) ? q : (sec == 1) ? k : v;
    mma_gemm_body(A, Wqkv, 3 * EE, bqkv, nullptr, sec, n0);
}

__global__ void __launch_bounds__(256, 2)
out_mma_kernel(const float* __restrict__ Wout, const float* __restrict__ bout,
               float* __restrict__ out)
{
    mma_gemm_body(g_ctx, Wout, EE, bout, out, 3, blockIdx.x << 7);
}

// ---------------------------------------------------------------------------
// Flash attention on tf32 mma: CTA = 64 queries, 4 warps x 16 rows,
// chunks of 64 keys. S=QK^T via mma, online softmax in regs, P->SMEM(tf32),
// O += P@V via mma.
// ---------------------------------------------------------------------------
__global__ void __launch_bounds__(128)
attn_mma_kernel(const int* __restrict__ mask)
{
    extern __shared__ char smraw[];
    uint32_t* Qs = (uint32_t*)smraw;     // [64][68] tf32 (pre-scaled)
    uint32_t* Ks = Qs + 64 * 68;         // [64][68]
    uint32_t* Vs = Ks + 64 * 68;         // [64][68]
    uint32_t* Ps = Vs + 64 * 68;         // [64][68]
    int* Msk = (int*)(Ps + 64 * 68);     // [64][64]

    const int tid = threadIdx.x, lane = tid & 31, wid = tid >> 5;
    const int g = lane >> 2, qp = lane & 3;
    const int bh = blockIdx.y, q0 = blockIdx.x << 6;
    const int w16 = wid << 4;
    const float* Qb = g_Q + (size_t)bh * SS * DD;
    const float* Kb = g_K + (size_t)bh * SS * DD;
    const float* Vb = g_V + (size_t)bh * SS * DD;

    // Q tile (scale by 1/sqrt(64) here)
    #pragma unroll
    for (int it = 0; it < 8; ++it) {
        int f = tid + (it << 7);
        int r = f >> 4, c = (f & 15) << 2;
        float4 v = *(const float4*)(Qb + (size_t)(q0 + r) * DD + c);
        uint4 u = make_uint4(f2tf(v.x * 0.125f), f2tf(v.y * 0.125f),
                             f2tf(v.z * 0.125f), f2tf(v.w * 0.125f));
        *(uint4*)&Qs[r * 68 + c] = u;
    }

    float o[8][4] = {};
    float mi0 = -1e30f, mi1 = -1e30f, li0 = 0.f, li1 = 0.f;

    for (int kc = 0; kc < SS; kc += 64) {
        __syncthreads();
        #pragma unroll
        for (int it = 0; it < 8; ++it) {
            int f = tid + (it << 7);
            int r = f >> 4, c = (f & 15) << 2;
            float4 kv = *(const float4*)(Kb + (size_t)(kc + r) * DD + c);
            *(uint4*)&Ks[r * 68 + c] =
                make_uint4(f2tf(kv.x), f2tf(kv.y), f2tf(kv.z), f2tf(kv.w));
            float4 vv = *(const float4*)(Vb + (size_t)(kc + r) * DD + c);
            *(uint4*)&Vs[r * 68 + c] =
                make_uint4(f2tf(vv.x), f2tf(vv.y), f2tf(vv.z), f2tf(vv.w));
            *(int4*)&Msk[r * 64 + c] = *(const int4*)(mask + (size_t)(q0 + r) * SS + kc + c);
        }
        __syncthreads();

        // S = Q @ K^T  (warp: 16 q-rows x 64 keys)
        float sacc[8][4] = {};
        #pragma unroll
        for (int ks = 0; ks < 8; ++ks) {
            uint32_t a[4];
            int mr = w16 + g;
            a[0] = Qs[mr * 68 + ks * 8 + qp];
            a[1] = Qs[(mr + 8) * 68 + ks * 8 + qp];
            a[2] = Qs[mr * 68 + ks * 8 + qp + 4];
            a[3] = Qs[(mr + 8) * 68 + ks * 8 + qp + 4];
            #pragma unroll
            for (int nf = 0; nf < 8; ++nf) {
                uint32_t b[2];
                b[0] = Ks[(nf * 8 + g) * 68 + ks * 8 + qp];
                b[1] = Ks[(nf * 8 + g) * 68 + ks * 8 + qp + 4];
                mma8(sacc[nf], a, b);
            }
        }

        // mask + row max
        float rm0 = -1e30f, rm1 = -1e30f;
        #pragma unroll
        for (int nf = 0; nf < 8; ++nf) {
            int col = nf * 8 + 2 * qp;
            int2 mv0 = *(const int2*)&Msk[(w16 + g) * 64 + col];
            int2 mv1 = *(const int2*)&Msk[(w16 + g + 8) * 64 + col];
            if (mv0.x == 0) sacc[nf][0] = -1e30f;
            if (mv0.y == 0) sacc[nf][1] = -1e30f;
            if (mv1.x == 0) sacc[nf][2] = -1e30f;
            if (mv1.y == 0) sacc[nf][3] = -1e30f;
            rm0 = fmaxf(rm0, fmaxf(sacc[nf][0], sacc[nf][1]));
            rm1 = fmaxf(rm1, fmaxf(sacc[nf][2], sacc[nf][3]));
        }
        rm0 = fmaxf(rm0, __shfl_xor_sync(0xffffffffu, rm0, 1));
        rm0 = fmaxf(rm0, __shfl_xor_sync(0xffffffffu, rm0, 2));
        rm1 = fmaxf(rm1, __shfl_xor_sync(0xffffffffu, rm1, 1));
        rm1 = fmaxf(rm1, __shfl_xor_sync(0xffffffffu, rm1, 2));

        float mn0 = fmaxf(mi0, rm0), mn1 = fmaxf(mi1, rm1);
        float al0 = __expf(mi0 - mn0), al1 = __expf(mi1 - mn1);
        mi0 = mn0; mi1 = mn1;

        float rs0 = 0.f, rs1 = 0.f;
        #pragma unroll
        for (int nf = 0; nf < 8; ++nf) {
            float p0 = __expf(sacc[nf][0] - mn0);
            float p1 = __expf(sacc[nf][1] - mn0);
            float p2 = __expf(sacc[nf][2] - mn1);
            float p3 = __expf(sacc[nf][3] - mn1);
            rs0 += p0 + p1; rs1 += p2 + p3;
            int col = nf * 8 + 2 * qp;
            *(uint2*)&Ps[(w16 + g) * 68 + col]     = make_uint2(f2tf(p0), f2tf(p1));
            *(uint2*)&Ps[(w16 + g + 8) * 68 + col] = make_uint2(f2tf(p2), f2tf(p3));
        }
        rs0 += __shfl_xor_sync(0xffffffffu, rs0, 1);
        rs0 += __shfl_xor_sync(0xffffffffu, rs0, 2);
        rs1 += __shfl_xor_sync(0xffffffffu, rs1, 1);
        rs1 += __shfl_xor_sync(0xffffffffu, rs1, 2);
        li0 = li0 * al0 + rs0;
        li1 = li1 * al1 + rs1;
        #pragma unroll
        for (int nf = 0; nf < 8; ++nf) {
            o[nf][0] *= al0; o[nf][1] *= al0;
            o[nf][2] *= al1; o[nf][3] *= al1;
        }
        __syncwarp();

        // O += P @ V  (k-dim = 64 keys)
        #pragma unroll
        for (int ks = 0; ks < 8; ++ks) {
            uint32_t a[4];
            int mr = w16 + g;
            a[0] = Ps[mr * 68 + ks * 8 + qp];
            a[1] = Ps[(mr + 8) * 68 + ks * 8 + qp];
            a[2] = Ps[mr * 68 + ks * 8 + qp + 4];
            a[3] = Ps[(mr + 8) * 68 + ks * 8 + qp + 4];
            #pragma unroll
            for (int nf = 0; nf < 8; ++nf) {
                uint32_t b[2];
                b[0] = Vs[(ks * 8 + qp) * 68 + nf * 8 + g];
                b[1] = Vs[(ks * 8 + qp + 4) * 68 + nf * 8 + g];
                mma8(o[nf], a, b);
            }
        }
        __syncwarp();
    }

    // epilogue: ctx[b][q][h*64+d]
    float inv0 = 1.0f / li0, inv1 = 1.0f / li1;
    int b = bh >> 4, h = bh & 15;
    #pragma unroll
    for (int nf = 0; nf < 8; ++nf) {
        int d = nf * 8 + 2 * qp;
        size_t r0 = (size_t)((b << 11) + q0 + w16 + g) * EE + (h << 6) + d;
        size_t r1 = (size_t)((b << 11) + q0 + w16 + g + 8) * EE + (h << 6) + d;
        *(float2*)(g_ctx + r0) = make_float2(o[nf][0] * inv0, o[nf][1] * inv0);
        *(float2*)(g_ctx + r1) = make_float2(o[nf][2] * inv1, o[nf][3] * inv1);
    }
}

#define ATTN_SMEM (4 * 64 * 68 * 4 + 64 * 64 * 4)   // 86016 B

// ---------------------------------------------------------------------------
extern "C" void kernel_launch(void* const* d_in, const int* in_sizes, int n_in,
                              void* d_out, int out_size)
{
    const float* q    = (const float*)d_in[0];
    const float* k    = (const float*)d_in[1];
    const float* v    = (const float*)d_in[2];
    const int*   mask = (const int*)  d_in[3];
    const float* Wqkv = (const float*)d_in[4];
    const float* bqkv = (const float*)d_in[5];
    const float* Wout = (const float*)d_in[6];
    const float* bout = (const float*)d_in[7];
    float* out = (float*)d_out;

    cudaFuncSetAttribute(attn_mma_kernel, cudaFuncAttributeMaxDynamicSharedMemorySize, ATTN_SMEM);

    // 1) fused QKV projection (tf32 mma.sync)
    qkv_mma_kernel<<<dim3(24, 32), 256>>>(q, k, v, Wqkv, bqkv);

    // 2) flash attention (tf32 mma.sync)
    attn_mma_kernel<<<dim3(SS / 64, BB * HH), 128, ATTN_SMEM>>>(mask);

    // 3) output projection (tf32 mma.sync)
    out_mma_kernel<<<dim3(8, 32), 256>>>(Wout, bout, out);
}

// round 5
// speedup vs baseline: 2.6035x; 1.2928x over previous
#include <cuda_runtime.h>
#include <cstdint>

// Problem constants
#define BB 2
#define SS 2048
#define EE 1024
#define HH 16
#define DD 64

// Scratch (device globals). All [bh][s][d] row-major.
__device__ float g_Q[BB*HH*SS*DD];
__device__ float g_K[BB*HH*SS*DD];
__device__ float g_V[BB*HH*SS*DD];
__device__ float g_ctx[BB*SS*EE];     // [b*s][e]

// ---------------------------------------------------------------------------
__device__ __forceinline__ uint32_t f2tf(float f){
    uint32_t r; asm("cvt.rna.tf32.f32 %0, %1;" : "=r"(r) : "f"(f)); return r;
}
__device__ __forceinline__ uint32_t smem_u32(const void* p){
    uint32_t a;
    asm("{ .reg .u64 t; cvta.to.shared.u64 t, %1; cvt.u32.u64 %0, t; }" : "=r"(a) : "l"(p));
    return a;
}
__device__ __forceinline__ void cp16(uint32_t dst, const void* src){
    asm volatile("cp.async.cg.shared.global [%0], [%1], 16;" :: "r"(dst), "l"(src));
}
#define CP_COMMIT() asm volatile("cp.async.commit_group;")
#define CP_WAIT1()  asm volatile("cp.async.wait_group 1;")
#define CP_WAIT0()  asm volatile("cp.async.wait_group 0;")

// m16n8k8 tf32 mma: D += A*B
__device__ __forceinline__ void mma8(float c[4], const uint32_t a[4], const uint32_t b[2]){
    asm volatile(
        "mma.sync.aligned.m16n8k8.row.col.f32.tf32.tf32.f32 "
        "{%0,%1,%2,%3}, {%4,%5,%6,%7}, {%8,%9}, {%0,%1,%2,%3};"
        : "+f"(c[0]), "+f"(c[1]), "+f"(c[2]), "+f"(c[3])
        : "r"(a[0]), "r"(a[1]), "r"(a[2]), "r"(a[3]), "r"(b[0]), "r"(b[1]));
}

// ---------------------------------------------------------------------------
// tf32 mma GEMM, cp.async 2-stage pipelined.
// C[4096, *] = A[4096,1024] @ W[:, n0:n0+128] + bias
// CTA 128x128, 8 warps (4m x 2n), warp tile 32x64, k-tile 32.
// ---------------------------------------------------------------------------
#define GA_LD 36
#define GB_LD 136
#define G_STAGE_W (128*GA_LD + 32*GB_LD)     // 8960 words
#define G_SMEM (2*G_STAGE_W*4)               // 71680 B

__device__ __forceinline__ void g_load_stage(uint32_t smb, int stage,
    const float* __restrict__ A, const float* __restrict__ W, int ldw,
    int n0, int m0, int kt, int tid)
{
    uint32_t abase = smb + stage * (G_STAGE_W * 4);
    uint32_t bbase = abase + 128 * GA_LD * 4;
    #pragma unroll
    for (int it = 0; it < 4; ++it) {
        int idx = tid + (it << 8);
        int r = idx >> 3, c = idx & 7;
        cp16(abase + r * (GA_LD*4) + c * 16, A + (size_t)(m0 + r) * EE + kt + c * 4);
    }
    #pragma unroll
    for (int it = 0; it < 4; ++it) {
        int idx = tid + (it << 8);
        int r = idx >> 5, c = idx & 31;
        cp16(bbase + r * (GB_LD*4) + c * 16, W + (size_t)(kt + r) * ldw + n0 + c * 4);
    }
}

__device__ __forceinline__ void mma_gemm_body(
    const float* __restrict__ A,
    const float* __restrict__ W, int ldw,
    const float* __restrict__ bias,
    float* __restrict__ Cout, int mode, int n0)
{
    extern __shared__ float smf[];
    const uint32_t smb = smem_u32(smf);
    const int tid = threadIdx.x, lane = tid & 31, wid = tid >> 5;
    const int g = lane >> 2, qp = lane & 3;
    const int m0 = blockIdx.y << 7;
    const int wm0 = (wid & 3) << 5;
    const int wn0 = (wid >> 2) << 6;

    float acc[2][8][4] = {};

    g_load_stage(smb, 0, A, W, ldw, n0, m0, 0, tid);
    CP_COMMIT();

    for (int t = 0; t < 32; ++t) {
        const int buf = t & 1;
        if (t < 31) { g_load_stage(smb, buf ^ 1, A, W, ldw, n0, m0, (t + 1) << 5, tid); CP_COMMIT(); CP_WAIT1(); }
        else        { CP_WAIT0(); }
        __syncthreads();

        const float* Asf = smf + buf * G_STAGE_W;
        const float* Bsf = Asf + 128 * GA_LD;
        #pragma unroll
        for (int ks = 0; ks < 4; ++ks) {
            uint32_t a[2][4];
            #pragma unroll
            for (int mf = 0; mf < 2; ++mf) {
                int mr = wm0 + mf * 16 + g;
                a[mf][0] = f2tf(Asf[mr * GA_LD + ks * 8 + qp]);
                a[mf][1] = f2tf(Asf[(mr + 8) * GA_LD + ks * 8 + qp]);
                a[mf][2] = f2tf(Asf[mr * GA_LD + ks * 8 + qp + 4]);
                a[mf][3] = f2tf(Asf[(mr + 8) * GA_LD + ks * 8 + qp + 4]);
            }
            #pragma unroll
            for (int nf = 0; nf < 8; ++nf) {
                uint32_t b[2];
                b[0] = f2tf(Bsf[(ks * 8 + qp) * GB_LD + wn0 + nf * 8 + g]);
                b[1] = f2tf(Bsf[(ks * 8 + qp + 4) * GB_LD + wn0 + nf * 8 + g]);
                mma8(acc[0][nf], a[0], b);
                mma8(acc[1][nf], a[1], b);
            }
        }
        __syncthreads();
    }

    #pragma unroll
    for (int mf = 0; mf < 2; ++mf) {
        #pragma unroll
        for (int nf = 0; nf < 8; ++nf) {
            int n = n0 + wn0 + nf * 8 + 2 * qp;
            float b0 = bias[n], b1 = bias[n + 1];
            #pragma unroll
            for (int rr = 0; rr < 2; ++rr) {
                int m = m0 + wm0 + mf * 16 + g + rr * 8;
                float2 val = make_float2(acc[mf][nf][rr * 2 + 0] + b0,
                                         acc[mf][nf][rr * 2 + 1] + b1);
                if (mode < 3) {
                    int nn = n & 1023;
                    int h = nn >> 6, d = nn & 63;
                    int b = m >> 11, s = m & (SS - 1);
                    float* dst = (mode == 0) ? g_Q : (mode == 1) ? g_K : g_V;
                    *(float2*)(dst + ((size_t)((b << 4) + h) * SS + s) * DD + d) = val;
                } else {
                    *(float2*)(Cout + (size_t)m * EE + n) = val;
                }
            }
        }
    }
}

__global__ void __launch_bounds__(256, 2)
qkv_mma_kernel(const float* __restrict__ q, const float* __restrict__ k,
               const float* __restrict__ v, const float* __restrict__ Wqkv,
               const float* __restrict__ bqkv)
{
    int n0 = blockIdx.x << 7;
    int sec = n0 >> 10;
    const float* A = (sec == 0) ? q : (sec == 1) ? k : v;
    mma_gemm_body(A, Wqkv, 3 * EE, bqkv, nullptr, sec, n0);
}

__global__ void __launch_bounds__(256, 2)
out_mma_kernel(const float* __restrict__ Wout, const float* __restrict__ bout,
               float* __restrict__ out)
{
    mma_gemm_body(g_ctx, Wout, EE, bout, out, 3, blockIdx.x << 7);
}

// ---------------------------------------------------------------------------
// Flash attention, tf32 mma, cp.async 2-stage pipelined K/V/mask.
// CTA: 128 queries, 256 threads (8 warps x 16 q-rows), key chunk 64.
// SMEM (words): Qs[128*68] @0 (tf32, prescaled), Ps[128*68] @8704,
//   stage s @ 17408 + s*17664: Ks[64*68] fp32, Vs[64*72] fp32, Msk[128*68] int
// ---------------------------------------------------------------------------
#define AQ_LD 68
#define AK_LD 68
#define AV_LD 72
#define AM_LD 68
#define A_PS_OFF   (128*AQ_LD)                         // 8704
#define A_ST_OFF   (A_PS_OFF + 128*AQ_LD)              // 17408
#define A_ST_W     (64*AK_LD + 64*AV_LD + 128*AM_LD)   // 17664
#define A_V_OFF    (64*AK_LD)
#define A_M_OFF    (64*AK_LD + 64*AV_LD)
#define ATTN_SMEM  ((A_ST_OFF + 2*A_ST_W) * 4)         // 210944 B

__device__ __forceinline__ void a_load_stage(uint32_t smb, int stage,
    const float* __restrict__ Kb, const float* __restrict__ Vb,
    const int* __restrict__ mask, int q0, int kc, int tid)
{
    uint32_t sbase = smb + (A_ST_OFF + stage * A_ST_W) * 4;
    #pragma unroll
    for (int it = 0; it < 4; ++it) {
        int idx = tid + (it << 8);
        int r = idx >> 4, c = idx & 15;
        cp16(sbase + r * (AK_LD*4) + c * 16, Kb + (size_t)(kc + r) * DD + c * 4);
        cp16(sbase + A_V_OFF*4 + r * (AV_LD*4) + c * 16, Vb + (size_t)(kc + r) * DD + c * 4);
    }
    #pragma unroll
    for (int it = 0; it < 8; ++it) {
        int idx = tid + (it << 8);
        int r = idx >> 4, c = idx & 15;
        cp16(sbase + A_M_OFF*4 + r * (AM_LD*4) + c * 16, mask + (size_t)(q0 + r) * SS + kc + c * 4);
    }
}

__global__ void __launch_bounds__(256, 1)
attn_mma_kernel(const int* __restrict__ mask)
{
    extern __shared__ float smf[];
    uint32_t* Qs = (uint32_t*)smf;
    uint32_t* Ps = (uint32_t*)smf + A_PS_OFF;
    const uint32_t smb = smem_u32(smf);

    const int tid = threadIdx.x, lane = tid & 31, wid = tid >> 5;
    const int g = lane >> 2, qp = lane & 3;
    const int bh = blockIdx.y, q0 = blockIdx.x << 7;
    const int w16 = wid << 4;
    const float* Qb = g_Q + (size_t)bh * SS * DD;
    const float* Kb = g_K + (size_t)bh * SS * DD;
    const float* Vb = g_V + (size_t)bh * SS * DD;

    // Q tile: load, scale by 1/8, convert to tf32 once
    #pragma unroll
    for (int it = 0; it < 8; ++it) {
        int f = tid + (it << 8);
        int r = f >> 4, c = (f & 15) << 2;
        float4 v = *(const float4*)(Qb + (size_t)(q0 + r) * DD + c);
        *(uint4*)&Qs[r * AQ_LD + c] =
            make_uint4(f2tf(v.x * 0.125f), f2tf(v.y * 0.125f),
                       f2tf(v.z * 0.125f), f2tf(v.w * 0.125f));
    }

    a_load_stage(smb, 0, Kb, Vb, mask, q0, 0, tid);
    CP_COMMIT();

    float o[8][4] = {};
    float mi0 = -1e30f, mi1 = -1e30f, li0 = 0.f, li1 = 0.f;

    for (int t = 0; t < 32; ++t) {
        const int buf = t & 1;
        if (t < 31) { a_load_stage(smb, buf ^ 1, Kb, Vb, mask, q0, (t + 1) << 6, tid); CP_COMMIT(); CP_WAIT1(); }
        else        { CP_WAIT0(); }
        __syncthreads();

        const float* Ksf = smf + A_ST_OFF + buf * A_ST_W;
        const float* Vsf = Ksf + A_V_OFF;
        const int*   Msk = (const int*)(Ksf + A_M_OFF);

        // S = Q @ K^T
        float sacc[8][4] = {};
        #pragma unroll
        for (int ks = 0; ks < 8; ++ks) {
            uint32_t a[4];
            int mr = w16 + g;
            a[0] = Qs[mr * AQ_LD + ks * 8 + qp];
            a[1] = Qs[(mr + 8) * AQ_LD + ks * 8 + qp];
            a[2] = Qs[mr * AQ_LD + ks * 8 + qp + 4];
            a[3] = Qs[(mr + 8) * AQ_LD + ks * 8 + qp + 4];
            #pragma unroll
            for (int nf = 0; nf < 8; ++nf) {
                uint32_t b[2];
                b[0] = f2tf(Ksf[(nf * 8 + g) * AK_LD + ks * 8 + qp]);
                b[1] = f2tf(Ksf[(nf * 8 + g) * AK_LD + ks * 8 + qp + 4]);
                mma8(sacc[nf], a, b);
            }
        }

        // mask + row max
        float rm0 = -1e30f, rm1 = -1e30f;
        #pragma unroll
        for (int nf = 0; nf < 8; ++nf) {
            int col = nf * 8 + 2 * qp;
            int2 mv0 = *(const int2*)&Msk[(w16 + g) * AM_LD + col];
            int2 mv1 = *(const int2*)&Msk[(w16 + g + 8) * AM_LD + col];
            if (mv0.x == 0) sacc[nf][0] = -1e30f;
            if (mv0.y == 0) sacc[nf][1] = -1e30f;
            if (mv1.x == 0) sacc[nf][2] = -1e30f;
            if (mv1.y == 0) sacc[nf][3] = -1e30f;
            rm0 = fmaxf(rm0, fmaxf(sacc[nf][0], sacc[nf][1]));
            rm1 = fmaxf(rm1, fmaxf(sacc[nf][2], sacc[nf][3]));
        }
        rm0 = fmaxf(rm0, __shfl_xor_sync(0xffffffffu, rm0, 1));
        rm0 = fmaxf(rm0, __shfl_xor_sync(0xffffffffu, rm0, 2));
        rm1 = fmaxf(rm1, __shfl_xor_sync(0xffffffffu, rm1, 1));
        rm1 = fmaxf(rm1, __shfl_xor_sync(0xffffffffu, rm1, 2));

        float mn0 = fmaxf(mi0, rm0), mn1 = fmaxf(mi1, rm1);
        float al0 = __expf(mi0 - mn0), al1 = __expf(mi1 - mn1);
        mi0 = mn0; mi1 = mn1;

        float rs0 = 0.f, rs1 = 0.f;
        #pragma unroll
        for (int nf = 0; nf < 8; ++nf) {
            float p0 = __expf(sacc[nf][0] - mn0);
            float p1 = __expf(sacc[nf][1] - mn0);
            float p2 = __expf(sacc[nf][2] - mn1);
            float p3 = __expf(sacc[nf][3] - mn1);
            rs0 += p0 + p1; rs1 += p2 + p3;
            int col = nf * 8 + 2 * qp;
            *(uint2*)&Ps[(w16 + g) * AQ_LD + col]     = make_uint2(f2tf(p0), f2tf(p1));
            *(uint2*)&Ps[(w16 + g + 8) * AQ_LD + col] = make_uint2(f2tf(p2), f2tf(p3));
        }
        rs0 += __shfl_xor_sync(0xffffffffu, rs0, 1);
        rs0 += __shfl_xor_sync(0xffffffffu, rs0, 2);
        rs1 += __shfl_xor_sync(0xffffffffu, rs1, 1);
        rs1 += __shfl_xor_sync(0xffffffffu, rs1, 2);
        li0 = li0 * al0 + rs0;
        li1 = li1 * al1 + rs1;
        #pragma unroll
        for (int nf = 0; nf < 8; ++nf) {
            o[nf][0] *= al0; o[nf][1] *= al0;
            o[nf][2] *= al1; o[nf][3] *= al1;
        }
        __syncwarp();

        // O += P @ V
        #pragma unroll
        for (int ks = 0; ks < 8; ++ks) {
            uint32_t a[4];
            int mr = w16 + g;
            a[0] = Ps[mr * AQ_LD + ks * 8 + qp];
            a[1] = Ps[(mr + 8) * AQ_LD + ks * 8 + qp];
            a[2] = Ps[mr * AQ_LD + ks * 8 + qp + 4];
            a[3] = Ps[(mr + 8) * AQ_LD + ks * 8 + qp + 4];
            #pragma unroll
            for (int nf = 0; nf < 8; ++nf) {
                uint32_t b[2];
                b[0] = f2tf(Vsf[(ks * 8 + qp) * AV_LD + nf * 8 + g]);
                b[1] = f2tf(Vsf[(ks * 8 + qp + 4) * AV_LD + nf * 8 + g]);
                mma8(o[nf], a, b);
            }
        }
        __syncthreads();   // stage buffer consumed; safe for next prefetch overwrite
    }

    // epilogue: ctx[b][q][h*64+d]
    float inv0 = 1.0f / li0, inv1 = 1.0f / li1;
    int b = bh >> 4, h = bh & 15;
    #pragma unroll
    for (int nf = 0; nf < 8; ++nf) {
        int d = nf * 8 + 2 * qp;
        size_t r0 = (size_t)((b << 11) + q0 + w16 + g) * EE + (h << 6) + d;
        size_t r1 = (size_t)((b << 11) + q0 + w16 + g + 8) * EE + (h << 6) + d;
        *(float2*)(g_ctx + r0) = make_float2(o[nf][0] * inv0, o[nf][1] * inv0);
        *(float2*)(g_ctx + r1) = make_float2(o[nf][2] * inv1, o[nf][3] * inv1);
    }
}

// ---------------------------------------------------------------------------
extern "C" void kernel_launch(void* const* d_in, const int* in_sizes, int n_in,
                              void* d_out, int out_size)
{
    const float* q    = (const float*)d_in[0];
    const float* k    = (const float*)d_in[1];
    const float* v    = (const float*)d_in[2];
    const int*   mask = (const int*)  d_in[3];
    const float* Wqkv = (const float*)d_in[4];
    const float* bqkv = (const float*)d_in[5];
    const float* Wout = (const float*)d_in[6];
    const float* bout = (const float*)d_in[7];
    float* out = (float*)d_out;

    static bool attr_done = false;
    if (!attr_done) {
        cudaFuncSetAttribute(qkv_mma_kernel, cudaFuncAttributeMaxDynamicSharedMemorySize, G_SMEM);
        cudaFuncSetAttribute(out_mma_kernel, cudaFuncAttributeMaxDynamicSharedMemorySize, G_SMEM);
        cudaFuncSetAttribute(attn_mma_kernel, cudaFuncAttributeMaxDynamicSharedMemorySize, ATTN_SMEM);
        attr_done = true;
    }

    qkv_mma_kernel<<<dim3(24, 32), 256, G_SMEM>>>(q, k, v, Wqkv, bqkv);
    attn_mma_kernel<<<dim3(SS / 128, BB * HH), 256, ATTN_SMEM>>>(mask);
    out_mma_kernel<<<dim3(8, 32), 256, G_SMEM>>>(Wout, bout, out);
}

// round 7
// speedup vs baseline: 2.7852x; 1.0698x over previous
#include <cuda_runtime.h>
#include <cstdint>

#define BB 2
#define SS 2048
#define EE 1024
#define HH 16
#define DD 64

// Scratch (device globals). tf32 bit patterns stored as uint32.
__device__ uint32_t g_Q [BB*HH*SS*DD];   // [bh][s][d], pre-scaled by 1/8, tf32
__device__ uint32_t g_K [BB*HH*SS*DD];   // [bh][s][d], tf32
__device__ uint32_t g_Vt[BB*HH*DD*SS];   // [bh][d][s], tf32 (transposed)
__device__ uint32_t g_ctx[BB*SS*EE];     // [b*s][e], tf32
__device__ uint32_t g_Wqt[3*EE*EE];      // Wqkv^T [3072][1024], tf32
__device__ uint32_t g_Wot[EE*EE];        // Wout^T [1024][1024], tf32
__device__ uint32_t g_mb[SS*(SS/32)];    // mask bitfield [2048][64]

// ---------------------------------------------------------------------------
__device__ __forceinline__ uint32_t f2tf(float f){
    uint32_t r; asm("cvt.rna.tf32.f32 %0, %1;" : "=r"(r) : "f"(f)); return r;
}
__device__ __forceinline__ uint32_t smem_u32(const void* p){
    uint32_t a;
    asm("{ .reg .u64 t; cvta.to.shared.u64 t, %1; cvt.u32.u64 %0, t; }" : "=r"(a) : "l"(p));
    return a;
}
__device__ __forceinline__ void cp16(uint32_t dst, const void* src){
    asm volatile("cp.async.cg.shared.global [%0], [%1], 16;" :: "r"(dst), "l"(src));
}
__device__ __forceinline__ void cp8(uint32_t dst, const void* src){
    asm volatile("cp.async.ca.shared.global [%0], [%1], 8;" :: "r"(dst), "l"(src));
}
#define CP_COMMIT() asm volatile("cp.async.commit_group;")
#define CP_WAIT1()  asm volatile("cp.async.wait_group 1;")
#define CP_WAIT0()  asm volatile("cp.async.wait_group 0;")

__device__ __forceinline__ void ldsm4(uint32_t addr, uint32_t r[4]){
    asm volatile("ldmatrix.sync.aligned.m8n8.x4.shared.b16 {%0,%1,%2,%3}, [%4];"
        : "=r"(r[0]), "=r"(r[1]), "=r"(r[2]), "=r"(r[3]) : "r"(addr));
}
__device__ __forceinline__ void mma8(float c[4], const uint32_t a[4], const uint32_t b[2]){
    asm volatile(
        "mma.sync.aligned.m16n8k8.row.col.f32.tf32.tf32.f32 "
        "{%0,%1,%2,%3}, {%4,%5,%6,%7}, {%8,%9}, {%0,%1,%2,%3};"
        : "+f"(c[0]), "+f"(c[1]), "+f"(c[2]), "+f"(c[3])
        : "r"(a[0]), "r"(a[1]), "r"(a[2]), "r"(a[3]), "r"(b[0]), "r"(b[1]));
}

// ---------------------------------------------------------------------------
// Prep kernels. NOTE: destination device globals are selected INSIDE device
// code (passing a __device__ symbol as a host-side kernel arg is invalid).
// ---------------------------------------------------------------------------
__global__ void wt_kernel(const float* __restrict__ W, int cols, int which)
{
    uint32_t* __restrict__ Wt = which ? g_Wot : g_Wqt;
    __shared__ uint32_t t[32][33];
    int n0 = blockIdx.x << 5, k0 = blockIdx.y << 5;
    int tx = threadIdx.x & 31, ty = threadIdx.x >> 5;   // 32x8
    #pragma unroll
    for (int j = 0; j < 32; j += 8)
        t[ty + j][tx] = f2tf(W[(size_t)(k0 + ty + j) * cols + n0 + tx]);
    __syncthreads();
    #pragma unroll
    for (int j = 0; j < 32; j += 8)
        Wt[(size_t)(n0 + ty + j) * EE + k0 + tx] = t[tx][ty + j];
}

__global__ void mask_pack_kernel(const int* __restrict__ mask)
{
    int w = (blockIdx.x << 3) + (threadIdx.x >> 5);     // word 0..63
    int s = blockIdx.y;
    int lane = threadIdx.x & 31;
    uint32_t bits = __ballot_sync(0xffffffffu, mask[(size_t)s * SS + (w << 5) + lane] != 0);
    if (lane == 0) g_mb[s * 64 + w] = bits;
}

// ---------------------------------------------------------------------------
// tf32 mma GEMM, cp.async 2-stage, ldmatrix fragments.
// A row-major [4096][1024] (fp32 if !ATF, tf32 bits if ATF); B = Wt[n][1024] tf32.
// CTA 128x128, 8 warps (4m x 2n), k-tile 32.
// ---------------------------------------------------------------------------
#define G_LD 36
#define G_BOFF (128*G_LD)            // words
#define G_STAGE_W (2*128*G_LD)       // 9216 words
#define G_SMEM (2*G_STAGE_W*4)       // 73728 B

template<bool ATF>
__device__ __forceinline__ void mma_gemm_body(
    const char* __restrict__ A,
    const uint32_t* __restrict__ Wt,
    const float* __restrict__ bias,
    float* __restrict__ Cout, int mode, int n0)
{
    extern __shared__ float smf[];
    const uint32_t smb = smem_u32(smf);
    const int tid = threadIdx.x, lane = tid & 31, wid = tid >> 5;
    const int g = lane >> 2, qp = lane & 3;
    const int m0 = blockIdx.y << 7;
    const int wm0 = (wid & 3) << 5, wn0 = (wid >> 2) << 6;
    const int rowT = (lane & 7) + ((lane >> 3) & 1) * 8;
    const int colW = (lane >> 4) << 2;

    uint32_t aBase[2], bBase[4];
    #pragma unroll
    for (int mf = 0; mf < 2; ++mf)
        aBase[mf] = smb + ((wm0 + mf * 16 + rowT) * G_LD + colW) * 4;
    #pragma unroll
    for (int p = 0; p < 4; ++p)
        bBase[p] = smb + (G_BOFF + (wn0 + p * 16 + rowT) * G_LD + colW) * 4;

    float acc[2][8][4] = {};

    #define G_LOAD(stage, kt) do { \
        uint32_t ab = smb + (stage) * (G_STAGE_W * 4); \
        uint32_t bb = ab + G_BOFF * 4; \
        _Pragma("unroll") \
        for (int it = 0; it < 4; ++it) { \
            int idx = tid + (it << 8); \
            int r = idx >> 3, c = idx & 7; \
            cp16(ab + r * (G_LD*4) + c * 16, A + ((size_t)(m0 + r) * EE + (kt) + c * 4) * 4); \
            cp16(bb + r * (G_LD*4) + c * 16, Wt + (size_t)(n0 + r) * EE + (kt) + c * 4); \
        } \
    } while (0)

    G_LOAD(0, 0);
    CP_COMMIT();

    for (int t = 0; t < 32; ++t) {
        const int buf = t & 1;
        if (t < 31) { G_LOAD(buf ^ 1, (t + 1) << 5); CP_COMMIT(); CP_WAIT1(); }
        else        { CP_WAIT0(); }
        __syncthreads();
        const uint32_t sOff = buf * (G_STAGE_W * 4);

        #pragma unroll
        for (int ks = 0; ks < 4; ++ks) {
            uint32_t a[2][4];
            #pragma unroll
            for (int mf = 0; mf < 2; ++mf) {
                ldsm4(aBase[mf] + sOff + ks * 32, a[mf]);
                if (!ATF) {
                    #pragma unroll
                    for (int x = 0; x < 4; ++x) a[mf][x] = f2tf(__uint_as_float(a[mf][x]));
                }
            }
            #pragma unroll
            for (int p = 0; p < 4; ++p) {
                uint32_t bq[4];
                ldsm4(bBase[p] + sOff + ks * 32, bq);
                uint32_t b0[2] = {bq[0], bq[2]};
                uint32_t b1[2] = {bq[1], bq[3]};
                mma8(acc[0][2*p],   a[0], b0);
                mma8(acc[1][2*p],   a[1], b0);
                mma8(acc[0][2*p+1], a[0], b1);
                mma8(acc[1][2*p+1], a[1], b1);
            }
        }
        __syncthreads();
    }

    // epilogue
    #pragma unroll
    for (int mf = 0; mf < 2; ++mf) {
        #pragma unroll
        for (int nf = 0; nf < 8; ++nf) {
            int n = n0 + wn0 + nf * 8 + 2 * qp;
            float b0v = bias[n], b1v = bias[n + 1];
            #pragma unroll
            for (int rr = 0; rr < 2; ++rr) {
                int m = m0 + wm0 + mf * 16 + g + rr * 8;
                float v0 = acc[mf][nf][rr * 2 + 0] + b0v;
                float v1 = acc[mf][nf][rr * 2 + 1] + b1v;
                if (mode == 3) {
                    *(float2*)(Cout + (size_t)m * EE + n) = make_float2(v0, v1);
                } else {
                    int nn = n & 1023;
                    int h = nn >> 6, d = nn & 63;
                    int b = m >> 11, s = m & (SS - 1);
                    int bh = (b << 4) + h;
                    if (mode == 0) {
                        *(uint2*)(g_Q + ((size_t)bh * SS + s) * DD + d) =
                            make_uint2(f2tf(v0 * 0.125f), f2tf(v1 * 0.125f));
                    } else if (mode == 1) {
                        *(uint2*)(g_K + ((size_t)bh * SS + s) * DD + d) =
                            make_uint2(f2tf(v0), f2tf(v1));
                    } else {
                        g_Vt[((size_t)bh * DD + d)     * SS + s] = f2tf(v0);
                        g_Vt[((size_t)bh * DD + d + 1) * SS + s] = f2tf(v1);
                    }
                }
            }
        }
    }
    #undef G_LOAD
}

__global__ void __launch_bounds__(256, 2)
qkv_mma_kernel(const float* __restrict__ q, const float* __restrict__ k,
               const float* __restrict__ v, const float* __restrict__ bqkv)
{
    int n0 = blockIdx.x << 7;
    int sec = n0 >> 10;
    const float* A = (sec == 0) ? q : (sec == 1) ? k : v;
    mma_gemm_body<false>((const char*)A, g_Wqt, bqkv, nullptr, sec, n0);
}

__global__ void __launch_bounds__(256, 2)
out_mma_kernel(const float* __restrict__ bout, float* __restrict__ out)
{
    mma_gemm_body<true>((const char*)g_ctx, g_Wot, bout, out, 3, blockIdx.x << 7);
}

// ---------------------------------------------------------------------------
// Flash attention: 128 queries/CTA, 256 threads (8 warps x 16 q-rows),
// key chunk 64, cp.async 2-stage on K/Vt/maskbits, ldmatrix fragments.
// SMEM words: Qs[128*68] @0, Ps[128*68] @8704,
//   stage s @17408+s*8960: Ks[64][68], Vt[64][68] @+4352, bm[128][2] @+8704
// ---------------------------------------------------------------------------
#define AQ_LD 68
#define A_PS_OFF 8704
#define A_ST_OFF 17408
#define A_ST_W   8960
#define A_VT_OFF 4352
#define A_BM_OFF 8704
#define ATTN_SMEM ((A_ST_OFF + 2*A_ST_W) * 4)   // 141312 B

__global__ void __launch_bounds__(256, 1)
attn_mma_kernel()
{
    extern __shared__ float smf[];
    uint32_t* Ps = (uint32_t*)smf + A_PS_OFF;
    const uint32_t smb = smem_u32(smf);

    const int tid = threadIdx.x, lane = tid & 31, wid = tid >> 5;
    const int g = lane >> 2, qp = lane & 3;
    const int bh = blockIdx.y, q0 = blockIdx.x << 7;
    const int w16 = wid << 4;
    const int rowT = (lane & 7) + ((lane >> 3) & 1) * 8;
    const int colW = (lane >> 4) << 2;

    const uint32_t* Qb = g_Q + (size_t)bh * SS * DD;
    const uint32_t* Kb = g_K + (size_t)bh * SS * DD;
    const uint32_t* Vb = g_Vt + (size_t)bh * DD * SS;

    // Q tile (already tf32 + prescaled): 128 rows x 64 words
    #pragma unroll
    for (int it = 0; it < 8; ++it) {
        int idx = tid + (it << 8);
        int r = idx >> 4, c = idx & 15;
        cp16(smb + r * (AQ_LD*4) + c * 16, Qb + (size_t)(q0 + r) * DD + c * 4);
    }

    #define A_LOAD(stage, kc) do { \
        uint32_t sbase = smb + (A_ST_OFF + (stage) * A_ST_W) * 4; \
        _Pragma("unroll") \
        for (int it = 0; it < 4; ++it) { \
            int idx = tid + (it << 8); \
            int r = idx >> 4, c = idx & 15; \
            cp16(sbase + r * (AQ_LD*4) + c * 16, Kb + (size_t)((kc) + r) * DD + c * 4); \
            cp16(sbase + A_VT_OFF*4 + r * (AQ_LD*4) + c * 16, Vb + (size_t)r * SS + (kc) + c * 4); \
        } \
        if (tid < 128) \
            cp8(sbase + A_BM_OFF*4 + tid * 8, g_mb + (size_t)(q0 + tid) * 64 + ((kc) >> 5)); \
    } while (0)

    A_LOAD(0, 0);
    CP_COMMIT();

    // fragment base addrs (bytes)
    const uint32_t qBase = smb + ((w16 + rowT) * AQ_LD + colW) * 4;
    const uint32_t pBase = smb + (A_PS_OFF + (w16 + rowT) * AQ_LD + colW) * 4;
    uint32_t kBase[4], vBase[4];
    #pragma unroll
    for (int p = 0; p < 4; ++p) {
        kBase[p] = ((p * 16 + rowT) * AQ_LD + colW) * 4;
        vBase[p] = kBase[p] + A_VT_OFF * 4;
    }

    float o[8][4] = {};
    float mi0 = -1e30f, mi1 = -1e30f, li0 = 0.f, li1 = 0.f;

    for (int t = 0; t < 32; ++t) {
        const int buf = t & 1;
        if (t < 31) { A_LOAD(buf ^ 1, (t + 1) << 6); CP_COMMIT(); CP_WAIT1(); }
        else        { CP_WAIT0(); }
        __syncthreads();
        const uint32_t sOff = smb + (A_ST_OFF + buf * A_ST_W) * 4;

        // S = Q @ K^T
        float sacc[8][4] = {};
        #pragma unroll
        for (int ks = 0; ks < 8; ++ks) {
            uint32_t a[4];
            ldsm4(qBase + ks * 32, a);
            #pragma unroll
            for (int p = 0; p < 4; ++p) {
                uint32_t bq[4];
                ldsm4(sOff + kBase[p] + ks * 32, bq);
                uint32_t b0[2] = {bq[0], bq[2]};
                uint32_t b1[2] = {bq[1], bq[3]};
                mma8(sacc[2*p],   a, b0);
                mma8(sacc[2*p+1], a, b1);
            }
        }

        // mask (bitfield) + row max
        const uint32_t* bmW = (const uint32_t*)smf + (A_ST_OFF + buf * A_ST_W + A_BM_OFF);
        uint2 m0 = *(const uint2*)(bmW + (w16 + g) * 2);
        uint2 m1 = *(const uint2*)(bmW + (w16 + g + 8) * 2);
        float rm0 = -1e30f, rm1 = -1e30f;
        #pragma unroll
        for (int nf = 0; nf < 8; ++nf) {
            int sh = (nf * 8 + 2 * qp) & 31;
            uint32_t w0 = (nf & 4) ? m0.y : m0.x;
            uint32_t w1 = (nf & 4) ? m1.y : m1.x;
            if (!((w0 >> sh) & 1u))       sacc[nf][0] = -1e30f;
            if (!((w0 >> (sh + 1)) & 1u)) sacc[nf][1] = -1e30f;
            if (!((w1 >> sh) & 1u))       sacc[nf][2] = -1e30f;
            if (!((w1 >> (sh + 1)) & 1u)) sacc[nf][3] = -1e30f;
            rm0 = fmaxf(rm0, fmaxf(sacc[nf][0], sacc[nf][1]));
            rm1 = fmaxf(rm1, fmaxf(sacc[nf][2], sacc[nf][3]));
        }
        rm0 = fmaxf(rm0, __shfl_xor_sync(0xffffffffu, rm0, 1));
        rm0 = fmaxf(rm0, __shfl_xor_sync(0xffffffffu, rm0, 2));
        rm1 = fmaxf(rm1, __shfl_xor_sync(0xffffffffu, rm1, 1));
        rm1 = fmaxf(rm1, __shfl_xor_sync(0xffffffffu, rm1, 2));

        float mn0 = fmaxf(mi0, rm0), mn1 = fmaxf(mi1, rm1);
        float al0 = __expf(mi0 - mn0), al1 = __expf(mi1 - mn1);
        mi0 = mn0; mi1 = mn1;

        float rs0 = 0.f, rs1 = 0.f;
        #pragma unroll
        for (int nf = 0; nf < 8; ++nf) {
            float p0 = __expf(sacc[nf][0] - mn0);
            float p1 = __expf(sacc[nf][1] - mn0);
            float p2 = __expf(sacc[nf][2] - mn1);
            float p3 = __expf(sacc[nf][3] - mn1);
            rs0 += p0 + p1; rs1 += p2 + p3;
            int col = nf * 8 + 2 * qp;
            *(uint2*)&Ps[(w16 + g) * AQ_LD + col]     = make_uint2(f2tf(p0), f2tf(p1));
            *(uint2*)&Ps[(w16 + g + 8) * AQ_LD + col] = make_uint2(f2tf(p2), f2tf(p3));
        }
        rs0 += __shfl_xor_sync(0xffffffffu, rs0, 1);
        rs0 += __shfl_xor_sync(0xffffffffu, rs0, 2);
        rs1 += __shfl_xor_sync(0xffffffffu, rs1, 1);
        rs1 += __shfl_xor_sync(0xffffffffu, rs1, 2);
        li0 = li0 * al0 + rs0;
        li1 = li1 * al1 + rs1;
        #pragma unroll
        for (int nf = 0; nf < 8; ++nf) {
            o[nf][0] *= al0; o[nf][1] *= al0;
            o[nf][2] *= al1; o[nf][3] *= al1;
        }
        __syncwarp();

        // O += P @ V   (B = Vt rows d, cols s)
        #pragma unroll
        for (int ks = 0; ks < 8; ++ks) {
            uint32_t a[4];
            ldsm4(pBase + ks * 32, a);
            #pragma unroll
            for (int p = 0; p < 4; ++p) {
                uint32_t bq[4];
                ldsm4(sOff + vBase[p] + ks * 32, bq);
                uint32_t b0[2] = {bq[0], bq[2]};
                uint32_t b1[2] = {bq[1], bq[3]};
                mma8(o[2*p],   a, b0);
                mma8(o[2*p+1], a, b1);
            }
        }
        __syncthreads();
    }

    // epilogue: ctx[b][q][h*64+d] as tf32
    float inv0 = 1.0f / li0, inv1 = 1.0f / li1;
    int b = bh >> 4, h = bh & 15;
    #pragma unroll
    for (int nf = 0; nf < 8; ++nf) {
        int d = nf * 8 + 2 * qp;
        size_t r0 = (size_t)((b << 11) + q0 + w16 + g) * EE + (h << 6) + d;
        size_t r1 = (size_t)((b << 11) + q0 + w16 + g + 8) * EE + (h << 6) + d;
        *(uint2*)(g_ctx + r0) = make_uint2(f2tf(o[nf][0] * inv0), f2tf(o[nf][1] * inv0));
        *(uint2*)(g_ctx + r1) = make_uint2(f2tf(o[nf][2] * inv1), f2tf(o[nf][3] * inv1));
    }
}

// ---------------------------------------------------------------------------
extern "C" void kernel_launch(void* const* d_in, const int* in_sizes, int n_in,
                              void* d_out, int out_size)
{
    const float* q    = (const float*)d_in[0];
    const float* k    = (const float*)d_in[1];
    const float* v    = (const float*)d_in[2];
    const int*   mask = (const int*)  d_in[3];
    const float* Wqkv = (const float*)d_in[4];
    const float* bqkv = (const float*)d_in[5];
    const float* Wout = (const float*)d_in[6];
    const float* bout = (const float*)d_in[7];
    float* out = (float*)d_out;

    cudaFuncSetAttribute(qkv_mma_kernel, cudaFuncAttributeMaxDynamicSharedMemorySize, G_SMEM);
    cudaFuncSetAttribute(out_mma_kernel, cudaFuncAttributeMaxDynamicSharedMemorySize, G_SMEM);
    cudaFuncSetAttribute(attn_mma_kernel, cudaFuncAttributeMaxDynamicSharedMemorySize, ATTN_SMEM);

    // prep: W transpose+tf32 (dst selected device-side), mask bit-pack
    wt_kernel<<<dim3(96, 32), 256>>>(Wqkv, 3 * EE, 0);
    wt_kernel<<<dim3(32, 32), 256>>>(Wout, EE, 1);
    mask_pack_kernel<<<dim3(8, SS), 256>>>(mask);

    // 1) fused QKV projection
    qkv_mma_kernel<<<dim3(24, 32), 256, G_SMEM>>>(q, k, v, bqkv);
    // 2) flash attention
    attn_mma_kernel<<<dim3(SS / 128, BB * HH), 256, ATTN_SMEM>>>();
    // 3) output projection
    out_mma_kernel<<<dim3(8, 32), 256, G_SMEM>>>(bout, out);
}

// round 9
// speedup vs baseline: 5.6132x; 2.0154x over previous
#include <cuda_runtime.h>
#include <cuda_fp16.h>
#include <cstdint>

#define BB 2
#define SS 2048
#define EE 1024
#define HH 16
#define DD 64

// Scratch (device globals), fp16 unless noted.
__device__ __half g_Xh[3*BB*SS*EE];      // converted q|k|v inputs [3][4096][1024]
__device__ __half g_Qh[BB*HH*SS*DD];     // [bh][s][d], pre-scaled by 1/8
__device__ __half g_Kh[BB*HH*SS*DD];     // [bh][s][d]
__device__ __half g_Vh[BB*HH*SS*DD];     // [bh][s][d]
__device__ __half g_ctxh[BB*SS*EE];      // [b*s][e]
__device__ __half g_Wqt[3*EE*EE];        // Wqkv^T [3072][1024]
__device__ __half g_Wot[EE*EE];          // Wout^T [1024][1024]
__device__ uint32_t g_mb[SS*(SS/32)];    // mask bitfield [2048][64]

// ---------------------------------------------------------------------------
__device__ __forceinline__ uint32_t smem_u32(const void* p){
    uint32_t a;
    asm("{ .reg .u64 t; cvta.to.shared.u64 t, %1; cvt.u32.u64 %0, t; }" : "=r"(a) : "l"(p));
    return a;
}
__device__ __forceinline__ void cp16(uint32_t dst, const void* src){
    asm volatile("cp.async.cg.shared.global [%0], [%1], 16;" :: "r"(dst), "l"(src));
}
__device__ __forceinline__ void cp8(uint32_t dst, const void* src){
    asm volatile("cp.async.ca.shared.global [%0], [%1], 8;" :: "r"(dst), "l"(src));
}
#define CP_COMMIT() asm volatile("cp.async.commit_group;")
#define CP_WAIT1()  asm volatile("cp.async.wait_group 1;")
#define CP_WAIT0()  asm volatile("cp.async.wait_group 0;")

__device__ __forceinline__ void ldsm4(uint32_t addr, uint32_t r[4]){
    asm volatile("ldmatrix.sync.aligned.m8n8.x4.shared.b16 {%0,%1,%2,%3}, [%4];"
        : "=r"(r[0]), "=r"(r[1]), "=r"(r[2]), "=r"(r[3]) : "r"(addr));
}
__device__ __forceinline__ void ldsm4t(uint32_t addr, uint32_t r[4]){
    asm volatile("ldmatrix.sync.aligned.m8n8.x4.trans.shared.b16 {%0,%1,%2,%3}, [%4];"
        : "=r"(r[0]), "=r"(r[1]), "=r"(r[2]), "=r"(r[3]) : "r"(addr));
}
// m16n8k16 fp16 mma, f32 accumulate: D += A*B
__device__ __forceinline__ void mma16(float c[4], const uint32_t a[4], uint32_t b0, uint32_t b1){
    asm volatile(
        "mma.sync.aligned.m16n8k16.row.col.f32.f16.f16.f32 "
        "{%0,%1,%2,%3}, {%4,%5,%6,%7}, {%8,%9}, {%0,%1,%2,%3};"
        : "+f"(c[0]), "+f"(c[1]), "+f"(c[2]), "+f"(c[3])
        : "r"(a[0]), "r"(a[1]), "r"(a[2]), "r"(a[3]), "r"(b0), "r"(b1));
}
__device__ __forceinline__ uint32_t packh2(float lo, float hi){
    __half2 h = __floats2half2_rn(lo, hi);
    return *(uint32_t*)&h;
}

// ---------------------------------------------------------------------------
// Prep kernels (device globals selected device-side)
// ---------------------------------------------------------------------------
__global__ void xh_kernel(const float* __restrict__ q, const float* __restrict__ k,
                          const float* __restrict__ v)
{
    int sec = blockIdx.y;
    const float* src = (sec == 0) ? q : (sec == 1) ? k : v;
    size_t i = ((size_t)blockIdx.x * 256 + threadIdx.x) * 8;
    float4 f0 = *(const float4*)(src + i);
    float4 f1 = *(const float4*)(src + i + 4);
    uint4 u;
    u.x = packh2(f0.x, f0.y); u.y = packh2(f0.z, f0.w);
    u.z = packh2(f1.x, f1.y); u.w = packh2(f1.z, f1.w);
    *(uint4*)(g_Xh + (size_t)sec * (BB*SS*EE) + i) = u;
}

__global__ void wt_kernel(const float* __restrict__ W, int cols, int which)
{
    __half* __restrict__ Wt = which ? g_Wot : g_Wqt;
    __shared__ float t[32][33];
    int n0 = blockIdx.x << 5, k0 = blockIdx.y << 5;
    int tx = threadIdx.x & 31, ty = threadIdx.x >> 5;   // 32x8
    #pragma unroll
    for (int j = 0; j < 32; j += 8)
        t[ty + j][tx] = W[(size_t)(k0 + ty + j) * cols + n0 + tx];
    __syncthreads();
    #pragma unroll
    for (int j = 0; j < 32; j += 8)
        Wt[(size_t)(n0 + ty + j) * EE + k0 + tx] = __float2half(t[tx][ty + j]);
}

__global__ void mask_pack_kernel(const int* __restrict__ mask)
{
    int w = (blockIdx.x << 3) + (threadIdx.x >> 5);
    int s = blockIdx.y;
    int lane = threadIdx.x & 31;
    uint32_t bits = __ballot_sync(0xffffffffu, mask[(size_t)s * SS + (w << 5) + lane] != 0);
    if (lane == 0) g_mb[s * 64 + w] = bits;
}

// ---------------------------------------------------------------------------
// fp16 mma GEMM: C[4096, *] = A[4096,1024] @ Wt[n][1024]^T + bias
// CTA 128x128, 8 warps (4m x 2n), k-tile 64 (4 x k16), cp.async 2-stage.
// Row stride 72 fp16 = 144 B (conflict-free ldmatrix).
// ---------------------------------------------------------------------------
#define GS 144
#define G_A_BYTES (128*GS)           // 18432
#define G_STAGE (2*G_A_BYTES)        // 36864
#define G_SMEM (2*G_STAGE)           // 73728

__device__ __forceinline__ void gemm_fp16(
    const __half* __restrict__ A,
    const __half* __restrict__ Wt,
    const float* __restrict__ bias,
    float* __restrict__ Cout, int mode, int n0)
{
    extern __shared__ char smc[];
    const uint32_t smb = smem_u32(smc);
    const int tid = threadIdx.x, lane = tid & 31, wid = tid >> 5;
    const int g = lane >> 2, qp = lane & 3;
    const int m0 = blockIdx.y << 7;
    const int wm0 = (wid & 3) << 5, wn0 = (wid >> 2) << 6;

    uint32_t aAddr[2], bAddr[4];
    #pragma unroll
    for (int mf = 0; mf < 2; ++mf)
        aAddr[mf] = smb + (wm0 + mf * 16 + (lane & 15)) * GS + ((lane >> 4) << 4);
    #pragma unroll
    for (int p = 0; p < 4; ++p)
        bAddr[p] = smb + G_A_BYTES
                 + (wn0 + p * 16 + ((lane >> 4) << 3) + (lane & 7)) * GS
                 + (((lane >> 3) & 1) << 4);

    float acc[2][8][4] = {};

    #define G_LOAD(stage, kt) do { \
        uint32_t ab = smb + (stage) * G_STAGE; \
        uint32_t bb = ab + G_A_BYTES; \
        _Pragma("unroll") \
        for (int it = 0; it < 4; ++it) { \
            int idx = tid + (it << 8); \
            int r = idx >> 3, c = idx & 7; \
            cp16(ab + r * GS + c * 16, A  + (size_t)(m0 + r) * EE + (kt) + c * 8); \
            cp16(bb + r * GS + c * 16, Wt + (size_t)(n0 + r) * EE + (kt) + c * 8); \
        } \
    } while (0)

    G_LOAD(0, 0);
    CP_COMMIT();

    for (int t = 0; t < 16; ++t) {
        const int buf = t & 1;
        if (t < 15) { G_LOAD(buf ^ 1, (t + 1) << 6); CP_COMMIT(); CP_WAIT1(); }
        else        { CP_WAIT0(); }
        __syncthreads();
        const uint32_t sOff = buf * G_STAGE;

        #pragma unroll
        for (int ks = 0; ks < 4; ++ks) {
            uint32_t a[2][4];
            ldsm4(aAddr[0] + sOff + ks * 32, a[0]);
            ldsm4(aAddr[1] + sOff + ks * 32, a[1]);
            #pragma unroll
            for (int p = 0; p < 4; ++p) {
                uint32_t bq[4];
                ldsm4(bAddr[p] + sOff + ks * 32, bq);
                mma16(acc[0][2*p],   a[0], bq[0], bq[1]);
                mma16(acc[1][2*p],   a[1], bq[0], bq[1]);
                mma16(acc[0][2*p+1], a[0], bq[2], bq[3]);
                mma16(acc[1][2*p+1], a[1], bq[2], bq[3]);
            }
        }
        __syncthreads();
    }

    // epilogue
    #pragma unroll
    for (int mf = 0; mf < 2; ++mf) {
        #pragma unroll
        for (int nf = 0; nf < 8; ++nf) {
            int n = n0 + wn0 + nf * 8 + 2 * qp;
            float b0v = bias[n], b1v = bias[n + 1];
            #pragma unroll
            for (int rr = 0; rr < 2; ++rr) {
                int m = m0 + wm0 + mf * 16 + g + rr * 8;
                float v0 = acc[mf][nf][rr * 2 + 0] + b0v;
                float v1 = acc[mf][nf][rr * 2 + 1] + b1v;
                if (mode == 3) {
                    *(float2*)(Cout + (size_t)m * EE + n) = make_float2(v0, v1);
                } else {
                    int nn = n & 1023;
                    int h = nn >> 6, d = nn & 63;
                    int b = m >> 11, s = m & (SS - 1);
                    size_t off = ((size_t)((b << 4) + h) * SS + s) * DD + d;
                    if (mode == 0)
                        *(uint32_t*)(g_Qh + off) = packh2(v0 * 0.125f, v1 * 0.125f);
                    else if (mode == 1)
                        *(uint32_t*)(g_Kh + off) = packh2(v0, v1);
                    else
                        *(uint32_t*)(g_Vh + off) = packh2(v0, v1);
                }
            }
        }
    }
    #undef G_LOAD
}

__global__ void __launch_bounds__(256, 2)
qkv_mma_kernel(const float* __restrict__ bqkv)
{
    int n0 = blockIdx.x << 7;
    int sec = n0 >> 10;
    gemm_fp16(g_Xh + (size_t)sec * (BB*SS*EE), g_Wqt, bqkv, nullptr, sec, n0);
}

__global__ void __launch_bounds__(256, 2)
out_mma_kernel(const float* __restrict__ bout, float* __restrict__ out)
{
    gemm_fp16(g_ctxh, g_Wot, bout, out, 3, blockIdx.x << 7);
}

// ---------------------------------------------------------------------------
// Flash attention fp16: 128 queries/CTA, 256 threads (8 warps x 16 q-rows),
// key chunk 64, cp.async 2-stage, P kept in registers (FA2 acc->A trick).
// SMEM bytes: Qs[128*144] @0; stage s @18432+s*19456: K[64*144], V @+9216, bm @+18432
// ---------------------------------------------------------------------------
#define AQ_BYTES (128*144)           // 18432
#define A_ST_W   19456
#define A_V_OFF  9216
#define A_BM_OFF 18432
#define ATTN_SMEM (AQ_BYTES + 2*A_ST_W)   // 57344

__global__ void __launch_bounds__(256, 2)
attn_mma_kernel()
{
    extern __shared__ char smc[];
    const uint32_t smb = smem_u32(smc);

    const int tid = threadIdx.x, lane = tid & 31, wid = tid >> 5;
    const int g = lane >> 2, qp = lane & 3;
    const int bh = blockIdx.y, q0 = blockIdx.x << 7;
    const int w16 = wid << 4;

    const __half* Qb = g_Qh + (size_t)bh * SS * DD;
    const __half* Kb = g_Kh + (size_t)bh * SS * DD;
    const __half* Vb = g_Vh + (size_t)bh * SS * DD;

    // Q tile: 128 rows x 64 fp16 (128B = 8 chunks/row)
    #pragma unroll
    for (int it = 0; it < 4; ++it) {
        int idx = tid + (it << 8);
        int r = idx >> 3, c = idx & 7;
        cp16(smb + r * 144 + c * 16, Qb + (size_t)(q0 + r) * DD + c * 8);
    }

    #define A_LOAD(stage, kc) do { \
        uint32_t sbase = smb + AQ_BYTES + (stage) * A_ST_W; \
        _Pragma("unroll") \
        for (int it = 0; it < 2; ++it) { \
            int idx = tid + (it << 8); \
            int r = idx >> 3, c = idx & 7; \
            cp16(sbase + r * 144 + c * 16, Kb + (size_t)((kc) + r) * DD + c * 8); \
            cp16(sbase + A_V_OFF + r * 144 + c * 16, Vb + (size_t)((kc) + r) * DD + c * 8); \
        } \
        if (tid < 128) \
            cp8(sbase + A_BM_OFF + tid * 8, g_mb + (size_t)(q0 + tid) * 64 + ((kc) >> 5)); \
    } while (0)

    A_LOAD(0, 0);
    CP_COMMIT();

    // fragment base addrs
    const uint32_t qBase = smb + (w16 + (lane & 15)) * 144 + ((lane >> 4) << 4);
    uint32_t kBase[4], vBase[4];
    #pragma unroll
    for (int p = 0; p < 4; ++p) {
        kBase[p] = (p * 16 + ((lane >> 4) << 3) + (lane & 7)) * 144 + (((lane >> 3) & 1) << 4);
        vBase[p] = A_V_OFF + (((lane >> 3) & 1) * 8 + (lane & 7)) * 144
                 + ((2 * p + (lane >> 4)) << 4);
    }

    float o[8][4] = {};
    float mi0 = -1e30f, mi1 = -1e30f, li0 = 0.f, li1 = 0.f;

    for (int t = 0; t < 32; ++t) {
        const int buf = t & 1;
        if (t < 31) { A_LOAD(buf ^ 1, (t + 1) << 6); CP_COMMIT(); CP_WAIT1(); }
        else        { CP_WAIT0(); }
        __syncthreads();
        const uint32_t sOff = smb + AQ_BYTES + buf * A_ST_W;

        // S = Q @ K^T
        float sacc[8][4] = {};
        #pragma unroll
        for (int ks = 0; ks < 4; ++ks) {
            uint32_t a[4];
            ldsm4(qBase + ks * 32, a);
            #pragma unroll
            for (int p = 0; p < 4; ++p) {
                uint32_t bq[4];
                ldsm4(sOff + kBase[p] + ks * 32, bq);
                mma16(sacc[2*p],   a, bq[0], bq[1]);
                mma16(sacc[2*p+1], a, bq[2], bq[3]);
            }
        }

        // mask (bitfield) + row max
        const uint32_t* bmW = (const uint32_t*)(smc + (sOff - smb) + A_BM_OFF);
        uint2 m0 = *(const uint2*)(bmW + (w16 + g) * 2);
        uint2 m1 = *(const uint2*)(bmW + (w16 + g + 8) * 2);
        float rm0 = -1e30f, rm1 = -1e30f;
        #pragma unroll
        for (int nf = 0; nf < 8; ++nf) {
            int sh = (nf * 8 + 2 * qp) & 31;
            uint32_t w0 = (nf & 4) ? m0.y : m0.x;
            uint32_t w1 = (nf & 4) ? m1.y : m1.x;
            if (!((w0 >> sh) & 1u))       sacc[nf][0] = -1e30f;
            if (!((w0 >> (sh + 1)) & 1u)) sacc[nf][1] = -1e30f;
            if (!((w1 >> sh) & 1u))       sacc[nf][2] = -1e30f;
            if (!((w1 >> (sh + 1)) & 1u)) sacc[nf][3] = -1e30f;
            rm0 = fmaxf(rm0, fmaxf(sacc[nf][0], sacc[nf][1]));
            rm1 = fmaxf(rm1, fmaxf(sacc[nf][2], sacc[nf][3]));
        }
        rm0 = fmaxf(rm0, __shfl_xor_sync(0xffffffffu, rm0, 1));
        rm0 = fmaxf(rm0, __shfl_xor_sync(0xffffffffu, rm0, 2));
        rm1 = fmaxf(rm1, __shfl_xor_sync(0xffffffffu, rm1, 1));
        rm1 = fmaxf(rm1, __shfl_xor_sync(0xffffffffu, rm1, 2));

        float mn0 = fmaxf(mi0, rm0), mn1 = fmaxf(mi1, rm1);
        float al0 = __expf(mi0 - mn0), al1 = __expf(mi1 - mn1);
        mi0 = mn0; mi1 = mn1;

        // exponentiate + pack P to fp16 A-fragments (registers only)
        uint32_t ph[8][2];
        float rs0 = 0.f, rs1 = 0.f;
        #pragma unroll
        for (int nf = 0; nf < 8; ++nf) {
            float p0 = __expf(sacc[nf][0] - mn0);
            float p1 = __expf(sacc[nf][1] - mn0);
            float p2 = __expf(sacc[nf][2] - mn1);
            float p3 = __expf(sacc[nf][3] - mn1);
            rs0 += p0 + p1; rs1 += p2 + p3;
            ph[nf][0] = packh2(p0, p1);
            ph[nf][1] = packh2(p2, p3);
        }
        rs0 += __shfl_xor_sync(0xffffffffu, rs0, 1);
        rs0 += __shfl_xor_sync(0xffffffffu, rs0, 2);
        rs1 += __shfl_xor_sync(0xffffffffu, rs1, 1);
        rs1 += __shfl_xor_sync(0xffffffffu, rs1, 2);
        li0 = li0 * al0 + rs0;
        li1 = li1 * al1 + rs1;
        #pragma unroll
        for (int nf = 0; nf < 8; ++nf) {
            o[nf][0] *= al0; o[nf][1] *= al0;
            o[nf][2] *= al1; o[nf][3] *= al1;
        }

        // O += P @ V  (P from registers, V via ldmatrix.trans)
        #pragma unroll
        for (int ks = 0; ks < 4; ++ks) {
            uint32_t a2[4] = { ph[2*ks][0], ph[2*ks][1], ph[2*ks+1][0], ph[2*ks+1][1] };
            #pragma unroll
            for (int p = 0; p < 4; ++p) {
                uint32_t bq[4];
                ldsm4t(sOff + vBase[p] + ks * (16 * 144), bq);
                mma16(o[2*p],   a2, bq[0], bq[1]);
                mma16(o[2*p+1], a2, bq[2], bq[3]);
            }
        }
        __syncthreads();
    }

    // epilogue: ctx[b][q][h*64+d] fp16
    float inv0 = 1.0f / li0, inv1 = 1.0f / li1;
    int b = bh >> 4, h = bh & 15;
    #pragma unroll
    for (int nf = 0; nf < 8; ++nf) {
        int d = nf * 8 + 2 * qp;
        size_t r0 = (size_t)((b << 11) + q0 + w16 + g) * EE + (h << 6) + d;
        size_t r1 = (size_t)((b << 11) + q0 + w16 + g + 8) * EE + (h << 6) + d;
        *(uint32_t*)(g_ctxh + r0) = packh2(o[nf][0] * inv0, o[nf][1] * inv0);
        *(uint32_t*)(g_ctxh + r1) = packh2(o[nf][2] * inv1, o[nf][3] * inv1);
    }
}

// ---------------------------------------------------------------------------
extern "C" void kernel_launch(void* const* d_in, const int* in_sizes, int n_in,
                              void* d_out, int out_size)
{
    const float* q    = (const float*)d_in[0];
    const float* k    = (const float*)d_in[1];
    const float* v    = (const float*)d_in[2];
    const int*   mask = (const int*)  d_in[3];
    const float* Wqkv = (const float*)d_in[4];
    const float* bqkv = (const float*)d_in[5];
    const float* Wout = (const float*)d_in[6];
    const float* bout = (const float*)d_in[7];
    float* out = (float*)d_out;

    cudaFuncSetAttribute(qkv_mma_kernel, cudaFuncAttributeMaxDynamicSharedMemorySize, G_SMEM);
    cudaFuncSetAttribute(out_mma_kernel, cudaFuncAttributeMaxDynamicSharedMemorySize, G_SMEM);
    cudaFuncSetAttribute(attn_mma_kernel, cudaFuncAttributeMaxDynamicSharedMemorySize, ATTN_SMEM);

    // prep: inputs->fp16, W transpose->fp16, mask bit-pack
    xh_kernel<<<dim3(2048, 3), 256>>>(q, k, v);
    wt_kernel<<<dim3(96, 32), 256>>>(Wqkv, 3 * EE, 0);
    wt_kernel<<<dim3(32, 32), 256>>>(Wout, EE, 1);
    mask_pack_kernel<<<dim3(8, SS), 256>>>(mask);

    // 1) fused QKV projection (fp16 mma)
    qkv_mma_kernel<<<dim3(24, 32), 256, G_SMEM>>>(bqkv);
    // 2) flash attention (fp16 mma, P in registers)
    attn_mma_kernel<<<dim3(SS / 128, BB * HH), 256, ATTN_SMEM>>>();
    // 3) output projection
    out_mma_kernel<<<dim3(8, 32), 256, G_SMEM>>>(bout, out);
}

// round 11
// speedup vs baseline: 6.3190x; 1.1257x over previous
#include <cuda_runtime.h>
#include <cuda_fp16.h>
#include <cstdint>

#define BB 2
#define SS 2048
#define EE 1024
#define HH 16
#define DD 64

// Q pre-scale: (1/sqrt(64)) * log2(e)  -> softmax computed in exp2 domain
#define QSCALE 0.18033688011112042f

// Scratch (device globals), fp16 unless noted.
__device__ __half g_Xh[3*BB*SS*EE];      // converted q|k|v inputs [3][4096][1024]
__device__ __half g_Qh[BB*HH*SS*DD];     // [bh][s][d], pre-scaled by log2e/8
__device__ __half g_Kh[BB*HH*SS*DD];     // [bh][s][d]
__device__ __half g_Vh[BB*HH*SS*DD];     // [bh][s][d]
__device__ __half g_ctxh[BB*SS*EE];      // [b*s][e]
__device__ __half g_Wqt[3*EE*EE];        // Wqkv^T [3072][1024]
__device__ __half g_Wot[EE*EE];          // Wout^T [1024][1024]
__device__ uint32_t g_mb[SS*(SS/32)];    // mask bitfield [2048][64]

// ---------------------------------------------------------------------------
__device__ __forceinline__ uint32_t smem_u32(const void* p){
    uint32_t a;
    asm("{ .reg .u64 t; cvta.to.shared.u64 t, %1; cvt.u32.u64 %0, t; }" : "=r"(a) : "l"(p));
    return a;
}
__device__ __forceinline__ void cp16(uint32_t dst, const void* src){
    asm volatile("cp.async.cg.shared.global [%0], [%1], 16;" :: "r"(dst), "l"(src));
}
__device__ __forceinline__ void cp8(uint32_t dst, const void* src){
    asm volatile("cp.async.ca.shared.global [%0], [%1], 8;" :: "r"(dst), "l"(src));
}
#define CP_COMMIT() asm volatile("cp.async.commit_group;")
#define CP_WAIT2()  asm volatile("cp.async.wait_group 2;")
#define CP_WAIT1()  asm volatile("cp.async.wait_group 1;")
#define CP_WAIT0()  asm volatile("cp.async.wait_group 0;")

__device__ __forceinline__ void ldsm4(uint32_t addr, uint32_t r[4]){
    asm volatile("ldmatrix.sync.aligned.m8n8.x4.shared.b16 {%0,%1,%2,%3}, [%4];"
        : "=r"(r[0]), "=r"(r[1]), "=r"(r[2]), "=r"(r[3]) : "r"(addr));
}
__device__ __forceinline__ void ldsm4t(uint32_t addr, uint32_t r[4]){
    asm volatile("ldmatrix.sync.aligned.m8n8.x4.trans.shared.b16 {%0,%1,%2,%3}, [%4];"
        : "=r"(r[0]), "=r"(r[1]), "=r"(r[2]), "=r"(r[3]) : "r"(addr));
}
__device__ __forceinline__ void mma16(float c[4], const uint32_t a[4], uint32_t b0, uint32_t b1){
    asm volatile(
        "mma.sync.aligned.m16n8k16.row.col.f32.f16.f16.f32 "
        "{%0,%1,%2,%3}, {%4,%5,%6,%7}, {%8,%9}, {%0,%1,%2,%3};"
        : "+f"(c[0]), "+f"(c[1]), "+f"(c[2]), "+f"(c[3])
        : "r"(a[0]), "r"(a[1]), "r"(a[2]), "r"(a[3]), "r"(b0), "r"(b1));
}
__device__ __forceinline__ uint32_t packh2(float lo, float hi){
    __half2 h = __floats2half2_rn(lo, hi);
    return *(uint32_t*)&h;
}
__device__ __forceinline__ uint32_t h2exp2(uint32_t d){
    uint32_t r; asm("ex2.approx.f16x2 %0, %1;" : "=r"(r) : "r"(d)); return r;
}

// ---------------------------------------------------------------------------
// Prep kernels
// ---------------------------------------------------------------------------
__global__ void xh_kernel(const float* __restrict__ q, const float* __restrict__ k,
                          const float* __restrict__ v)
{
    int sec = blockIdx.y;
    const float* src = (sec == 0) ? q : (sec == 1) ? k : v;
    size_t i = ((size_t)blockIdx.x * 256 + threadIdx.x) * 8;
    float4 f0 = *(const float4*)(src + i);
    float4 f1 = *(const float4*)(src + i + 4);
    uint4 u;
    u.x = packh2(f0.x, f0.y); u.y = packh2(f0.z, f0.w);
    u.z = packh2(f1.x, f1.y); u.w = packh2(f1.z, f1.w);
    *(uint4*)(g_Xh + (size_t)sec * (BB*SS*EE) + i) = u;
}

__global__ void wt_kernel(const float* __restrict__ W, int cols, int which)
{
    __half* __restrict__ Wt = which ? g_Wot : g_Wqt;
    __shared__ float t[32][33];
    int n0 = blockIdx.x << 5, k0 = blockIdx.y << 5;
    int tx = threadIdx.x & 31, ty = threadIdx.x >> 5;
    #pragma unroll
    for (int j = 0; j < 32; j += 8)
        t[ty + j][tx] = W[(size_t)(k0 + ty + j) * cols + n0 + tx];
    __syncthreads();
    #pragma unroll
    for (int j = 0; j < 32; j += 8)
        Wt[(size_t)(n0 + ty + j) * EE + k0 + tx] = __float2half(t[tx][ty + j]);
}

// 8 bitfield words per warp
__global__ void mask_pack_kernel(const int* __restrict__ mask)
{
    int gw = (blockIdx.x * 256 + threadIdx.x) >> 5;   // 0..16383
    int lane = threadIdx.x & 31;
    int s = gw >> 3;
    int w0 = (gw & 7) << 3;
    const int* base = mask + (size_t)s * SS + (w0 << 5) + lane;
    uint32_t out[8];
    #pragma unroll
    for (int j = 0; j < 8; ++j)
        out[j] = __ballot_sync(0xffffffffu, base[j * 32] != 0);
    if (lane == 0) {
        *(uint4*)(g_mb + (size_t)s * 64 + w0)     = make_uint4(out[0], out[1], out[2], out[3]);
        *(uint4*)(g_mb + (size_t)s * 64 + w0 + 4) = make_uint4(out[4], out[5], out[6], out[7]);
    }
}

// ---------------------------------------------------------------------------
// fp16 mma GEMM: 3-stage cp.async ring, depth-1 prefetch, ONE barrier/iter.
// CTA 128x128, 8 warps (4m x 2n), k-tile 64.
// ---------------------------------------------------------------------------
#define GS 144
#define G_A_BYTES (128*GS)           // 18432
#define G_STAGE (2*G_A_BYTES)        // 36864
#define G_SMEM (3*G_STAGE)           // 110592

__device__ __forceinline__ void gemm_fp16(
    const __half* __restrict__ A,
    const __half* __restrict__ Wt,
    const float* __restrict__ bias,
    float* __restrict__ Cout, int mode, int n0)
{
    extern __shared__ char smc[];
    const uint32_t smb = smem_u32(smc);
    const int tid = threadIdx.x, lane = tid & 31, wid = tid >> 5;
    const int g = lane >> 2, qp = lane & 3;
    const int m0 = blockIdx.y << 7;
    const int wm0 = (wid & 3) << 5, wn0 = (wid >> 2) << 6;

    uint32_t aAddr[2], bAddr[4];
    #pragma unroll
    for (int mf = 0; mf < 2; ++mf)
        aAddr[mf] = smb + (wm0 + mf * 16 + (lane & 15)) * GS + ((lane >> 4) << 4);
    #pragma unroll
    for (int p = 0; p < 4; ++p)
        bAddr[p] = smb + G_A_BYTES
                 + (wn0 + p * 16 + ((lane >> 4) << 3) + (lane & 7)) * GS
                 + (((lane >> 3) & 1) << 4);

    float acc[2][8][4] = {};

    #define G_LOAD(stage, kt) do { \
        uint32_t ab = smb + (stage) * G_STAGE; \
        uint32_t bb = ab + G_A_BYTES; \
        _Pragma("unroll") \
        for (int it = 0; it < 4; ++it) { \
            int idx = tid + (it << 8); \
            int r = idx >> 3, c = idx & 7; \
            cp16(ab + r * GS + c * 16, A  + (size_t)(m0 + r) * EE + (kt) + c * 8); \
            cp16(bb + r * GS + c * 16, Wt + (size_t)(n0 + r) * EE + (kt) + c * 8); \
        } \
    } while (0)

    G_LOAD(0, 0);
    CP_COMMIT();

    int cur = 0, nxt = 1;
    for (int t = 0; t < 16; ++t) {
        if (t < 15) { G_LOAD(nxt, (t + 1) << 6); CP_COMMIT(); CP_WAIT1(); }
        else        { CP_WAIT0(); }
        __syncthreads();
        const uint32_t sOff = cur * G_STAGE;

        #pragma unroll
        for (int ks = 0; ks < 4; ++ks) {
            uint32_t a[2][4];
            ldsm4(aAddr[0] + sOff + ks * 32, a[0]);
            ldsm4(aAddr[1] + sOff + ks * 32, a[1]);
            #pragma unroll
            for (int p = 0; p < 4; ++p) {
                uint32_t bq[4];
                ldsm4(bAddr[p] + sOff + ks * 32, bq);
                mma16(acc[0][2*p],   a[0], bq[0], bq[1]);
                mma16(acc[1][2*p],   a[1], bq[0], bq[1]);
                mma16(acc[0][2*p+1], a[0], bq[2], bq[3]);
                mma16(acc[1][2*p+1], a[1], bq[2], bq[3]);
            }
        }
        cur = nxt; nxt = (nxt == 2) ? 0 : nxt + 1;
    }

    // epilogue
    #pragma unroll
    for (int mf = 0; mf < 2; ++mf) {
        #pragma unroll
        for (int nf = 0; nf < 8; ++nf) {
            int n = n0 + wn0 + nf * 8 + 2 * qp;
            float b0v = bias[n], b1v = bias[n + 1];
            #pragma unroll
            for (int rr = 0; rr < 2; ++rr) {
                int m = m0 + wm0 + mf * 16 + g + rr * 8;
                float v0 = acc[mf][nf][rr * 2 + 0] + b0v;
                float v1 = acc[mf][nf][rr * 2 + 1] + b1v;
                if (mode == 3) {
                    *(float2*)(Cout + (size_t)m * EE + n) = make_float2(v0, v1);
                } else {
                    int nn = n & 1023;
                    int h = nn >> 6, d = nn & 63;
                    int b = m >> 11, s = m & (SS - 1);
                    size_t off = ((size_t)((b << 4) + h) * SS + s) * DD + d;
                    if (mode == 0)
                        *(uint32_t*)(g_Qh + off) = packh2(v0 * QSCALE, v1 * QSCALE);
                    else if (mode == 1)
                        *(uint32_t*)(g_Kh + off) = packh2(v0, v1);
                    else
                        *(uint32_t*)(g_Vh + off) = packh2(v0, v1);
                }
            }
        }
    }
    #undef G_LOAD
}

__global__ void __launch_bounds__(256, 2)
qkv_mma_kernel(const float* __restrict__ bqkv)
{
    int n0 = blockIdx.x << 7;
    int sec = n0 >> 10;
    gemm_fp16(g_Xh + (size_t)sec * (BB*SS*EE), g_Wqt, bqkv, nullptr, sec, n0);
}

__global__ void __launch_bounds__(256, 2)
out_mma_kernel(const float* __restrict__ bout, float* __restrict__ out)
{
    gemm_fp16(g_ctxh, g_Wot, bout, out, 3, blockIdx.x << 7);
}

// ---------------------------------------------------------------------------
// Flash attention fp16: 128 queries/CTA, 256 threads, chunk 64,
// 4-stage cp.async ring (depth-2 prefetch), ONE barrier/iter,
// Q fragments register-resident, softmax via ex2.approx.f16x2 (log2 domain).
// ---------------------------------------------------------------------------
#define AQ_BYTES (128*144)           // 18432
#define A_ST_W   19456
#define A_V_OFF  9216
#define A_BM_OFF 18432
#define ATTN_SMEM (AQ_BYTES + 4*A_ST_W)   // 96256

__global__ void __launch_bounds__(256, 2)
attn_mma_kernel()
{
    extern __shared__ char smc[];
    const uint32_t smb = smem_u32(smc);

    const int tid = threadIdx.x, lane = tid & 31, wid = tid >> 5;
    const int g = lane >> 2, qp = lane & 3;
    const int bh = blockIdx.y, q0 = blockIdx.x << 7;
    const int w16 = wid << 4;

    const __half* Qb = g_Qh + (size_t)bh * SS * DD;
    const __half* Kb = g_Kh + (size_t)bh * SS * DD;
    const __half* Vb = g_Vh + (size_t)bh * SS * DD;

    // Q tile cp.async (group with stage 0)
    #pragma unroll
    for (int it = 0; it < 4; ++it) {
        int idx = tid + (it << 8);
        int r = idx >> 3, c = idx & 7;
        cp16(smb + r * 144 + c * 16, Qb + (size_t)(q0 + r) * DD + c * 8);
    }

    #define A_LOAD(stage, kc) do { \
        uint32_t sbase = smb + AQ_BYTES + (stage) * A_ST_W; \
        _Pragma("unroll") \
        for (int it = 0; it < 2; ++it) { \
            int idx = tid + (it << 8); \
            int r = idx >> 3, c = idx & 7; \
            cp16(sbase + r * 144 + c * 16, Kb + (size_t)((kc) + r) * DD + c * 8); \
            cp16(sbase + A_V_OFF + r * 144 + c * 16, Vb + (size_t)((kc) + r) * DD + c * 8); \
        } \
        if (tid < 128) \
            cp8(sbase + A_BM_OFF + tid * 8, g_mb + (size_t)(q0 + tid) * 64 + ((kc) >> 5)); \
    } while (0)

    A_LOAD(0, 0);
    CP_COMMIT();        // g0 = Q + stage0
    A_LOAD(1, 64);
    CP_COMMIT();        // g1

    // fragment base addrs
    const uint32_t qBase = smb + (w16 + (lane & 15)) * 144 + ((lane >> 4) << 4);
    uint32_t kBase[4], vBase[4];
    #pragma unroll
    for (int p = 0; p < 4; ++p) {
        kBase[p] = (p * 16 + ((lane >> 4) << 3) + (lane & 7)) * 144 + (((lane >> 3) & 1) << 4);
        vBase[p] = A_V_OFF + (((lane >> 3) & 1) * 8 + (lane & 7)) * 144
                 + ((2 * p + (lane >> 4)) << 4);
    }

    // Q fragments -> registers (constant across all chunks)
    CP_WAIT1();
    __syncthreads();
    uint32_t qa[4][4];
    #pragma unroll
    for (int ks = 0; ks < 4; ++ks) ldsm4(qBase + ks * 32, qa[ks]);

    float o[8][4] = {};
    float mi0 = -1e30f, mi1 = -1e30f, li0 = 0.f, li1 = 0.f;

    for (int t = 0; t < 32; ++t) {
        if (t < 30)      { A_LOAD((t + 2) & 3, (t + 2) << 6); CP_COMMIT(); CP_WAIT2(); }
        else if (t == 30){ CP_WAIT1(); }
        else             { CP_WAIT0(); }
        __syncthreads();
        const uint32_t sOff = smb + AQ_BYTES + (t & 3) * A_ST_W;

        // S = Q @ K^T  (log2-domain scores; Q pre-scaled by log2e/8)
        float sacc[8][4] = {};
        #pragma unroll
        for (int ks = 0; ks < 4; ++ks) {
            #pragma unroll
            for (int p = 0; p < 4; ++p) {
                uint32_t bq[4];
                ldsm4(sOff + kBase[p] + ks * 32, bq);
                mma16(sacc[2*p],   qa[ks], bq[0], bq[1]);
                mma16(sacc[2*p+1], qa[ks], bq[2], bq[3]);
            }
        }

        // mask (bitfield) + row max
        const uint32_t* bmW = (const uint32_t*)(smc + (sOff - smb) + A_BM_OFF);
        uint2 m0 = *(const uint2*)(bmW + (w16 + g) * 2);
        uint2 m1 = *(const uint2*)(bmW + (w16 + g + 8) * 2);
        float rm0 = -1e30f, rm1 = -1e30f;
        #pragma unroll
        for (int nf = 0; nf < 8; ++nf) {
            int sh = (nf * 8 + 2 * qp) & 31;
            uint32_t w0 = (nf & 4) ? m0.y : m0.x;
            uint32_t w1 = (nf & 4) ? m1.y : m1.x;
            if (!((w0 >> sh) & 1u))       sacc[nf][0] = -1e30f;
            if (!((w0 >> (sh + 1)) & 1u)) sacc[nf][1] = -1e30f;
            if (!((w1 >> sh) & 1u))       sacc[nf][2] = -1e30f;
            if (!((w1 >> (sh + 1)) & 1u)) sacc[nf][3] = -1e30f;
            rm0 = fmaxf(rm0, fmaxf(sacc[nf][0], sacc[nf][1]));
            rm1 = fmaxf(rm1, fmaxf(sacc[nf][2], sacc[nf][3]));
        }
        rm0 = fmaxf(rm0, __shfl_xor_sync(0xffffffffu, rm0, 1));
        rm0 = fmaxf(rm0, __shfl_xor_sync(0xffffffffu, rm0, 2));
        rm1 = fmaxf(rm1, __shfl_xor_sync(0xffffffffu, rm1, 1));
        rm1 = fmaxf(rm1, __shfl_xor_sync(0xffffffffu, rm1, 2));

        float mn0 = fmaxf(mi0, rm0), mn1 = fmaxf(mi1, rm1);
        float al0 = exp2f(mi0 - mn0), al1 = exp2f(mi1 - mn1);
        mi0 = mn0; mi1 = mn1;

        // P = 2^(s - m) via fp16x2 MUFU; row sums from the SAME quantized ps
        uint32_t ph[8][2];
        float rs0 = 0.f, rs1 = 0.f;
        #pragma unroll
        for (int nf = 0; nf < 8; ++nf) {
            uint32_t hp0 = h2exp2(packh2(sacc[nf][0] - mn0, sacc[nf][1] - mn0));
            uint32_t hp1 = h2exp2(packh2(sacc[nf][2] - mn1, sacc[nf][3] - mn1));
            ph[nf][0] = hp0;
            ph[nf][1] = hp1;
            float2 f0 = __half22float2(*(__half2*)&hp0);
            float2 f1 = __half22float2(*(__half2*)&hp1);
            rs0 += f0.x + f0.y;
            rs1 += f1.x + f1.y;
        }
        rs0 += __shfl_xor_sync(0xffffffffu, rs0, 1);
        rs0 += __shfl_xor_sync(0xffffffffu, rs0, 2);
        rs1 += __shfl_xor_sync(0xffffffffu, rs1, 1);
        rs1 += __shfl_xor_sync(0xffffffffu, rs1, 2);
        li0 = li0 * al0 + rs0;
        li1 = li1 * al1 + rs1;
        #pragma unroll
        for (int nf = 0; nf < 8; ++nf) {
            o[nf][0] *= al0; o[nf][1] *= al0;
            o[nf][2] *= al1; o[nf][3] *= al1;
        }

        // O += P @ V  (P from registers, V via ldmatrix.trans)
        #pragma unroll
        for (int ks = 0; ks < 4; ++ks) {
            uint32_t a2[4] = { ph[2*ks][0], ph[2*ks][1], ph[2*ks+1][0], ph[2*ks+1][1] };
            #pragma unroll
            for (int p = 0; p < 4; ++p) {
                uint32_t bq[4];
                ldsm4t(sOff + vBase[p] + ks * (16 * 144), bq);
                mma16(o[2*p],   a2, bq[0], bq[1]);
                mma16(o[2*p+1], a2, bq[2], bq[3]);
            }
        }
    }

    // epilogue: ctx[b][q][h*64+d] fp16
    float inv0 = 1.0f / li0, inv1 = 1.0f / li1;
    int b = bh >> 4, h = bh & 15;
    #pragma unroll
    for (int nf = 0; nf < 8; ++nf) {
        int d = nf * 8 + 2 * qp;
        size_t r0 = (size_t)((b << 11) + q0 + w16 + g) * EE + (h << 6) + d;
        size_t r1 = (size_t)((b << 11) + q0 + w16 + g + 8) * EE + (h << 6) + d;
        *(uint32_t*)(g_ctxh + r0) = packh2(o[nf][0] * inv0, o[nf][1] * inv0);
        *(uint32_t*)(g_ctxh + r1) = packh2(o[nf][2] * inv1, o[nf][3] * inv1);
    }
}

// ---------------------------------------------------------------------------
extern "C" void kernel_launch(void* const* d_in, const int* in_sizes, int n_in,
                              void* d_out, int out_size)
{
    const float* q    = (const float*)d_in[0];
    const float* k    = (const float*)d_in[1];
    const float* v    = (const float*)d_in[2];
    const int*   mask = (const int*)  d_in[3];
    const float* Wqkv = (const float*)d_in[4];
    const float* bqkv = (const float*)d_in[5];
    const float* Wout = (const float*)d_in[6];
    const float* bout = (const float*)d_in[7];
    float* out = (float*)d_out;

    cudaFuncSetAttribute(qkv_mma_kernel, cudaFuncAttributeMaxDynamicSharedMemorySize, G_SMEM);
    cudaFuncSetAttribute(out_mma_kernel, cudaFuncAttributeMaxDynamicSharedMemorySize, G_SMEM);
    cudaFuncSetAttribute(attn_mma_kernel, cudaFuncAttributeMaxDynamicSharedMemorySize, ATTN_SMEM);

    // prep
    xh_kernel<<<dim3(2048, 3), 256>>>(q, k, v);
    wt_kernel<<<dim3(96, 32), 256>>>(Wqkv, 3 * EE, 0);
    wt_kernel<<<dim3(32, 32), 256>>>(Wout, EE, 1);
    mask_pack_kernel<<<2048, 256>>>(mask);

    // 1) fused QKV projection
    qkv_mma_kernel<<<dim3(24, 32), 256, G_SMEM>>>(bqkv);
    // 2) flash attention
    attn_mma_kernel<<<dim3(SS / 128, BB * HH), 256, ATTN_SMEM>>>();
    // 3) output projection
    out_mma_kernel<<<dim3(8, 32), 256, G_SMEM>>>(bout, out);
}

// round 13
// speedup vs baseline: 6.5563x; 1.0376x over previous
#include <cuda_runtime.h>
#include <cuda_fp16.h>
#include <cstdint>

#define BB 2
#define SS 2048
#define EE 1024
#define HH 16
#define DD 64

// Q pre-scale: (1/sqrt(64)) * log2(e)  -> softmax computed in exp2 domain
#define QSCALE 0.18033688011112042f

// Scratch (device globals), fp16 unless noted.
__device__ __half g_Xh[3*BB*SS*EE];      // converted q|k|v inputs [3][4096][1024]
__device__ __half g_Qh[BB*HH*SS*DD];     // [bh][s][d], pre-scaled by log2e/8
__device__ __half g_Kh[BB*HH*SS*DD];     // [bh][s][d]
__device__ __half g_Vh[BB*HH*SS*DD];     // [bh][s][d]
__device__ __half g_ctxh[BB*SS*EE];      // [b*s][e]
__device__ __half g_Wqt[3*EE*EE];        // Wqkv^T [3072][1024]
__device__ __half g_Wot[EE*EE];          // Wout^T [1024][1024]
__device__ uint32_t g_mb[SS*(SS/32)];    // mask bitfield [2048][64]

// ---------------------------------------------------------------------------
__device__ __forceinline__ uint32_t smem_u32(const void* p){
    uint32_t a;
    asm("{ .reg .u64 t; cvta.to.shared.u64 t, %1; cvt.u32.u64 %0, t; }" : "=r"(a) : "l"(p));
    return a;
}
__device__ __forceinline__ void cp16(uint32_t dst, const void* src){
    asm volatile("cp.async.cg.shared.global [%0], [%1], 16;" :: "r"(dst), "l"(src));
}
__device__ __forceinline__ void cp8(uint32_t dst, const void* src){
    asm volatile("cp.async.ca.shared.global [%0], [%1], 8;" :: "r"(dst), "l"(src));
}
#define CP_COMMIT() asm volatile("cp.async.commit_group;")
#define CP_WAIT2()  asm volatile("cp.async.wait_group 2;")
#define CP_WAIT1()  asm volatile("cp.async.wait_group 1;")
#define CP_WAIT0()  asm volatile("cp.async.wait_group 0;")

__device__ __forceinline__ void ldsm4(uint32_t addr, uint32_t r[4]){
    asm volatile("ldmatrix.sync.aligned.m8n8.x4.shared.b16 {%0,%1,%2,%3}, [%4];"
        : "=r"(r[0]), "=r"(r[1]), "=r"(r[2]), "=r"(r[3]) : "r"(addr));
}
__device__ __forceinline__ void ldsm4t(uint32_t addr, uint32_t r[4]){
    asm volatile("ldmatrix.sync.aligned.m8n8.x4.trans.shared.b16 {%0,%1,%2,%3}, [%4];"
        : "=r"(r[0]), "=r"(r[1]), "=r"(r[2]), "=r"(r[3]) : "r"(addr));
}
__device__ __forceinline__ void mma16(float c[4], const uint32_t a[4], uint32_t b0, uint32_t b1){
    asm volatile(
        "mma.sync.aligned.m16n8k16.row.col.f32.f16.f16.f32 "
        "{%0,%1,%2,%3}, {%4,%5,%6,%7}, {%8,%9}, {%0,%1,%2,%3};"
        : "+f"(c[0]), "+f"(c[1]), "+f"(c[2]), "+f"(c[3])
        : "r"(a[0]), "r"(a[1]), "r"(a[2]), "r"(a[3]), "r"(b0), "r"(b1));
}
__device__ __forceinline__ uint32_t packh2(float lo, float hi){
    __half2 h = __floats2half2_rn(lo, hi);
    return *(uint32_t*)&h;
}
__device__ __forceinline__ uint32_t h2exp2(uint32_t d){
    uint32_t r; asm("ex2.approx.f16x2 %0, %1;" : "=r"(r) : "r"(d)); return r;
}

// ---------------------------------------------------------------------------
// Fused prep kernel: block ranges dispatch the 4 former prep kernels.
//  [0,6144)      xh: fp32 q|k|v -> fp16
//  [6144,9216)   Wqkv transpose -> fp16   (96 x 32 tiles)
//  [9216,10240)  Wout transpose -> fp16   (32 x 32 tiles)
//  [10240,12288) mask bit-pack
// ---------------------------------------------------------------------------
__global__ void prep_kernel(const float* __restrict__ q, const float* __restrict__ k,
                            const float* __restrict__ v, const float* __restrict__ Wqkv,
                            const float* __restrict__ Wout, const int* __restrict__ mask)
{
    const int blk = blockIdx.x;
    const int tid = threadIdx.x;

    if (blk < 6144) {
        int sec = blk / 2048;
        const float* src = (sec == 0) ? q : (sec == 1) ? k : v;
        size_t i = ((size_t)(blk % 2048) * 256 + tid) * 8;
        float4 f0 = *(const float4*)(src + i);
        float4 f1 = *(const float4*)(src + i + 4);
        uint4 u;
        u.x = packh2(f0.x, f0.y); u.y = packh2(f0.z, f0.w);
        u.z = packh2(f1.x, f1.y); u.w = packh2(f1.z, f1.w);
        *(uint4*)(g_Xh + (size_t)sec * (BB*SS*EE) + i) = u;
    } else if (blk < 10240) {
        __shared__ float t[32][33];
        int isout = (blk >= 9216);
        int bb = blk - (isout ? 9216 : 6144);
        int nblk = isout ? 32 : 96;
        int cols = isout ? EE : 3 * EE;
        const float* W = isout ? Wout : Wqkv;
        __half* Wt = isout ? g_Wot : g_Wqt;
        int n0 = (bb % nblk) << 5, k0 = (bb / nblk) << 5;
        int tx = tid & 31, ty = tid >> 5;
        #pragma unroll
        for (int j = 0; j < 32; j += 8)
            t[ty + j][tx] = W[(size_t)(k0 + ty + j) * cols + n0 + tx];
        __syncthreads();
        #pragma unroll
        for (int j = 0; j < 32; j += 8)
            Wt[(size_t)(n0 + ty + j) * EE + k0 + tx] = __float2half(t[tx][ty + j]);
    } else {
        int gw = ((blk - 10240) * 256 + tid) >> 5;
        int lane = tid & 31;
        int s = gw >> 3;
        int w0 = (gw & 7) << 3;
        const int* base = mask + (size_t)s * SS + (w0 << 5) + lane;
        uint32_t out[8];
        #pragma unroll
        for (int j = 0; j < 8; ++j)
            out[j] = __ballot_sync(0xffffffffu, base[j * 32] != 0);
        if (lane == 0) {
            *(uint4*)(g_mb + (size_t)s * 64 + w0)     = make_uint4(out[0], out[1], out[2], out[3]);
            *(uint4*)(g_mb + (size_t)s * 64 + w0 + 4) = make_uint4(out[4], out[5], out[6], out[7]);
        }
    }
}

// ---------------------------------------------------------------------------
// fp16 mma GEMM: 3-stage cp.async ring, depth-1 prefetch, ONE barrier/iter.
// CTA 128x128, 8 warps (4m x 2n), k-tile 64.
// ---------------------------------------------------------------------------
#define GS 144
#define G_A_BYTES (128*GS)           // 18432
#define G_STAGE (2*G_A_BYTES)        // 36864
#define G_SMEM (3*G_STAGE)           // 110592

__device__ __forceinline__ void gemm_fp16(
    const __half* __restrict__ A,
    const __half* __restrict__ Wt,
    const float* __restrict__ bias,
    float* __restrict__ Cout, int mode, int n0)
{
    extern __shared__ char smc[];
    const uint32_t smb = smem_u32(smc);
    const int tid = threadIdx.x, lane = tid & 31, wid = tid >> 5;
    const int g = lane >> 2, qp = lane & 3;
    const int m0 = blockIdx.y << 7;
    const int wm0 = (wid & 3) << 5, wn0 = (wid >> 2) << 6;

    uint32_t aAddr[2], bAddr[4];
    #pragma unroll
    for (int mf = 0; mf < 2; ++mf)
        aAddr[mf] = smb + (wm0 + mf * 16 + (lane & 15)) * GS + ((lane >> 4) << 4);
    #pragma unroll
    for (int p = 0; p < 4; ++p)
        bAddr[p] = smb + G_A_BYTES
                 + (wn0 + p * 16 + ((lane >> 4) << 3) + (lane & 7)) * GS
                 + (((lane >> 3) & 1) << 4);

    float acc[2][8][4] = {};

    #define G_LOAD(stage, kt) do { \
        uint32_t ab = smb + (stage) * G_STAGE; \
        uint32_t bb = ab + G_A_BYTES; \
        _Pragma("unroll") \
        for (int it = 0; it < 4; ++it) { \
            int idx = tid + (it << 8); \
            int r = idx >> 3, c = idx & 7; \
            cp16(ab + r * GS + c * 16, A  + (size_t)(m0 + r) * EE + (kt) + c * 8); \
            cp16(bb + r * GS + c * 16, Wt + (size_t)(n0 + r) * EE + (kt) + c * 8); \
        } \
    } while (0)

    G_LOAD(0, 0);
    CP_COMMIT();

    int cur = 0, nxt = 1;
    for (int t = 0; t < 16; ++t) {
        if (t < 15) { G_LOAD(nxt, (t + 1) << 6); CP_COMMIT(); CP_WAIT1(); }
        else        { CP_WAIT0(); }
        __syncthreads();
        const uint32_t sOff = cur * G_STAGE;

        #pragma unroll
        for (int ks = 0; ks < 4; ++ks) {
            uint32_t a[2][4];
            ldsm4(aAddr[0] + sOff + ks * 32, a[0]);
            ldsm4(aAddr[1] + sOff + ks * 32, a[1]);
            #pragma unroll
            for (int p = 0; p < 4; ++p) {
                uint32_t bq[4];
                ldsm4(bAddr[p] + sOff + ks * 32, bq);
                mma16(acc[0][2*p],   a[0], bq[0], bq[1]);
                mma16(acc[1][2*p],   a[1], bq[0], bq[1]);
                mma16(acc[0][2*p+1], a[0], bq[2], bq[3]);
                mma16(acc[1][2*p+1], a[1], bq[2], bq[3]);
            }
        }
        cur = nxt; nxt = (nxt == 2) ? 0 : nxt + 1;
    }

    // epilogue
    #pragma unroll
    for (int mf = 0; mf < 2; ++mf) {
        #pragma unroll
        for (int nf = 0; nf < 8; ++nf) {
            int n = n0 + wn0 + nf * 8 + 2 * qp;
            float b0v = bias[n], b1v = bias[n + 1];
            #pragma unroll
            for (int rr = 0; rr < 2; ++rr) {
                int m = m0 + wm0 + mf * 16 + g + rr * 8;
                float v0 = acc[mf][nf][rr * 2 + 0] + b0v;
                float v1 = acc[mf][nf][rr * 2 + 1] + b1v;
                if (mode == 3) {
                    *(float2*)(Cout + (size_t)m * EE + n) = make_float2(v0, v1);
                } else {
                    int nn = n & 1023;
                    int h = nn >> 6, d = nn & 63;
                    int b = m >> 11, s = m & (SS - 1);
                    size_t off = ((size_t)((b << 4) + h) * SS + s) * DD + d;
                    if (mode == 0)
                        *(uint32_t*)(g_Qh + off) = packh2(v0 * QSCALE, v1 * QSCALE);
                    else if (mode == 1)
                        *(uint32_t*)(g_Kh + off) = packh2(v0, v1);
                    else
                        *(uint32_t*)(g_Vh + off) = packh2(v0, v1);
                }
            }
        }
    }
    #undef G_LOAD
}

__global__ void __launch_bounds__(256, 2)
qkv_mma_kernel(const float* __restrict__ bqkv)
{
    int n0 = blockIdx.x << 7;
    int sec = n0 >> 10;
    gemm_fp16(g_Xh + (size_t)sec * (BB*SS*EE), g_Wqt, bqkv, nullptr, sec, n0);
}

__global__ void __launch_bounds__(256, 2)
out_mma_kernel(const float* __restrict__ bout, float* __restrict__ out)
{
    gemm_fp16(g_ctxh, g_Wot, bout, out, 3, blockIdx.x << 7);
}

// ---------------------------------------------------------------------------
// Flash attention fp16: 128 queries/CTA, 256 threads, chunk 64,
// 4-stage cp.async ring (depth-2 prefetch), ONE barrier/iter,
// Q fragments register-resident, softmax via ex2.approx.f16x2.
// Max reduced as packed half2 (2 shuffles); l-reduction deferred to epilogue.
// ---------------------------------------------------------------------------
#define AQ_BYTES (128*144)           // 18432
#define A_ST_W   19456
#define A_V_OFF  9216
#define A_BM_OFF 18432
#define ATTN_SMEM (AQ_BYTES + 4*A_ST_W)   // 96256

__global__ void __launch_bounds__(256, 2)
attn_mma_kernel()
{
    extern __shared__ char smc[];
    const uint32_t smb = smem_u32(smc);

    const int tid = threadIdx.x, lane = tid & 31, wid = tid >> 5;
    const int g = lane >> 2, qp = lane & 3;
    const int bh = blockIdx.y, q0 = blockIdx.x << 7;
    const int w16 = wid << 4;

    const __half* Qb = g_Qh + (size_t)bh * SS * DD;
    const __half* Kb = g_Kh + (size_t)bh * SS * DD;
    const __half* Vb = g_Vh + (size_t)bh * SS * DD;

    // Q tile cp.async (group with stage 0)
    #pragma unroll
    for (int it = 0; it < 4; ++it) {
        int idx = tid + (it << 8);
        int r = idx >> 3, c = idx & 7;
        cp16(smb + r * 144 + c * 16, Qb + (size_t)(q0 + r) * DD + c * 8);
    }

    #define A_LOAD(stage, kc) do { \
        uint32_t sbase = smb + AQ_BYTES + (stage) * A_ST_W; \
        _Pragma("unroll") \
        for (int it = 0; it < 2; ++it) { \
            int idx = tid + (it << 8); \
            int r = idx >> 3, c = idx & 7; \
            cp16(sbase + r * 144 + c * 16, Kb + (size_t)((kc) + r) * DD + c * 8); \
            cp16(sbase + A_V_OFF + r * 144 + c * 16, Vb + (size_t)((kc) + r) * DD + c * 8); \
        } \
        if (tid < 128) \
            cp8(sbase + A_BM_OFF + tid * 8, g_mb + (size_t)(q0 + tid) * 64 + ((kc) >> 5)); \
    } while (0)

    A_LOAD(0, 0);
    CP_COMMIT();        // g0 = Q + stage0
    A_LOAD(1, 64);
    CP_COMMIT();        // g1

    // fragment base addrs
    const uint32_t qBase = smb + (w16 + (lane & 15)) * 144 + ((lane >> 4) << 4);
    uint32_t kBase[4], vBase[4];
    #pragma unroll
    for (int p = 0; p < 4; ++p) {
        kBase[p] = (p * 16 + ((lane >> 4) << 3) + (lane & 7)) * 144 + (((lane >> 3) & 1) << 4);
        vBase[p] = A_V_OFF + (((lane >> 3) & 1) * 8 + (lane & 7)) * 144
                 + ((2 * p + (lane >> 4)) << 4);
    }

    // Q fragments -> registers (constant across all chunks)
    CP_WAIT1();
    __syncthreads();
    uint32_t qa[4][4];
    #pragma unroll
    for (int ks = 0; ks < 4; ++ks) ldsm4(qBase + ks * 32, qa[ks]);

    float o[8][4] = {};
    __half2 mih = __floats2half2_rn(-60000.f, -60000.f);   // (m_row0, m_row1)
    float li0 = 0.f, li1 = 0.f;                            // per-lane partial sums

    for (int t = 0; t < 32; ++t) {
        if (t < 30)      { A_LOAD((t + 2) & 3, (t + 2) << 6); CP_COMMIT(); CP_WAIT2(); }
        else if (t == 30){ CP_WAIT1(); }
        else             { CP_WAIT0(); }
        __syncthreads();
        const uint32_t sOff = smb + AQ_BYTES + (t & 3) * A_ST_W;

        // mask bits first: LDS latency hides under the QK MMAs below
        const uint32_t* bmW = (const uint32_t*)(smc + (sOff - smb) + A_BM_OFF);
        uint2 m0 = *(const uint2*)(bmW + (w16 + g) * 2);
        uint2 m1 = *(const uint2*)(bmW + (w16 + g + 8) * 2);

        // S = Q @ K^T  (log2-domain scores; Q pre-scaled by log2e/8)
        float sacc[8][4] = {};
        #pragma unroll
        for (int ks = 0; ks < 4; ++ks) {
            #pragma unroll
            for (int p = 0; p < 4; ++p) {
                uint32_t bq[4];
                ldsm4(sOff + kBase[p] + ks * 32, bq);
                mma16(sacc[2*p],   qa[ks], bq[0], bq[1]);
                mma16(sacc[2*p+1], qa[ks], bq[2], bq[3]);
            }
        }

        // mask + per-thread row max
        float rm0 = -1e30f, rm1 = -1e30f;
        #pragma unroll
        for (int nf = 0; nf < 8; ++nf) {
            int sh = (nf * 8 + 2 * qp) & 31;
            uint32_t w0 = (nf & 4) ? m0.y : m0.x;
            uint32_t w1 = (nf & 4) ? m1.y : m1.x;
            if (!((w0 >> sh) & 1u))       sacc[nf][0] = -1e30f;
            if (!((w0 >> (sh + 1)) & 1u)) sacc[nf][1] = -1e30f;
            if (!((w1 >> sh) & 1u))       sacc[nf][2] = -1e30f;
            if (!((w1 >> (sh + 1)) & 1u)) sacc[nf][3] = -1e30f;
            rm0 = fmaxf(rm0, fmaxf(sacc[nf][0], sacc[nf][1]));
            rm1 = fmaxf(rm1, fmaxf(sacc[nf][2], sacc[nf][3]));
        }
        // packed half2 max reduction across the 4 qp lanes (2 shuffles)
        uint32_t rmh = packh2(rm0, rm1);
        { __half2 a2 = *(__half2*)&rmh;
          uint32_t s1 = __shfl_xor_sync(0xffffffffu, rmh, 1);
          a2 = __hmax2(a2, *(__half2*)&s1);
          uint32_t ab = *(uint32_t*)&a2;
          uint32_t s2 = __shfl_xor_sync(0xffffffffu, ab, 2);
          a2 = __hmax2(a2, *(__half2*)&s2);
          rmh = *(uint32_t*)&a2; }
        __half2 mnh = __hmax2(mih, *(__half2*)&rmh);
        float mn0 = __low2float(mnh),  mn1 = __high2float(mnh);
        float al0 = exp2f(__low2float(mih) - mn0);
        float al1 = exp2f(__high2float(mih) - mn1);
        mih = mnh;

        // P = 2^(s - m) via fp16x2 MUFU; per-lane partial row sums (no shuffles)
        uint32_t ph[8][2];
        float rs0 = 0.f, rs1 = 0.f;
        #pragma unroll
        for (int nf = 0; nf < 8; ++nf) {
            uint32_t hp0 = h2exp2(packh2(sacc[nf][0] - mn0, sacc[nf][1] - mn0));
            uint32_t hp1 = h2exp2(packh2(sacc[nf][2] - mn1, sacc[nf][3] - mn1));
            ph[nf][0] = hp0;
            ph[nf][1] = hp1;
            float2 f0 = __half22float2(*(__half2*)&hp0);
            float2 f1 = __half22float2(*(__half2*)&hp1);
            rs0 += f0.x + f0.y;
            rs1 += f1.x + f1.y;
        }
        li0 = li0 * al0 + rs0;
        li1 = li1 * al1 + rs1;
        if (!(al0 == 1.f && al1 == 1.f)) {
            #pragma unroll
            for (int nf = 0; nf < 8; ++nf) {
                o[nf][0] *= al0; o[nf][1] *= al0;
                o[nf][2] *= al1; o[nf][3] *= al1;
            }
        }

        // O += P @ V  (P from registers, V via ldmatrix.trans)
        #pragma unroll
        for (int ks = 0; ks < 4; ++ks) {
            uint32_t a2[4] = { ph[2*ks][0], ph[2*ks][1], ph[2*ks+1][0], ph[2*ks+1][1] };
            #pragma unroll
            for (int p = 0; p < 4; ++p) {
                uint32_t bq[4];
                ldsm4t(sOff + vBase[p] + ks * (16 * 144), bq);
                mma16(o[2*p],   a2, bq[0], bq[1]);
                mma16(o[2*p+1], a2, bq[2], bq[3]);
            }
        }
    }

    // deferred l-reduction across the 4 qp lanes (once, not per chunk)
    li0 += __shfl_xor_sync(0xffffffffu, li0, 1);
    li0 += __shfl_xor_sync(0xffffffffu, li0, 2);
    li1 += __shfl_xor_sync(0xffffffffu, li1, 1);
    li1 += __shfl_xor_sync(0xffffffffu, li1, 2);

    // epilogue: ctx[b][q][h*64+d] fp16
    float inv0 = 1.0f / li0, inv1 = 1.0f / li1;
    int b = bh >> 4, h = bh & 15;
    #pragma unroll
    for (int nf = 0; nf < 8; ++nf) {
        int d = nf * 8 + 2 * qp;
        size_t r0 = (size_t)((b << 11) + q0 + w16 + g) * EE + (h << 6) + d;
        size_t r1 = (size_t)((b << 11) + q0 + w16 + g + 8) * EE + (h << 6) + d;
        *(uint32_t*)(g_ctxh + r0) = packh2(o[nf][0] * inv0, o[nf][1] * inv0);
        *(uint32_t*)(g_ctxh + r1) = packh2(o[nf][2] * inv1, o[nf][3] * inv1);
    }
}

// ---------------------------------------------------------------------------
extern "C" void kernel_launch(void* const* d_in, const int* in_sizes, int n_in,
                              void* d_out, int out_size)
{
    const float* q    = (const float*)d_in[0];
    const float* k    = (const float*)d_in[1];
    const float* v    = (const float*)d_in[2];
    const int*   mask = (const int*)  d_in[3];
    const float* Wqkv = (const float*)d_in[4];
    const float* bqkv = (const float*)d_in[5];
    const float* Wout = (const float*)d_in[6];
    const float* bout = (const float*)d_in[7];
    float* out = (float*)d_out;

    cudaFuncSetAttribute(qkv_mma_kernel, cudaFuncAttributeMaxDynamicSharedMemorySize, G_SMEM);
    cudaFuncSetAttribute(out_mma_kernel, cudaFuncAttributeMaxDynamicSharedMemorySize, G_SMEM);
    cudaFuncSetAttribute(attn_mma_kernel, cudaFuncAttributeMaxDynamicSharedMemorySize, ATTN_SMEM);

    // fused prep (one launch)
    prep_kernel<<<12288, 256>>>(q, k, v, Wqkv, Wout, mask);

    // 1) fused QKV projection
    qkv_mma_kernel<<<dim3(24, 32), 256, G_SMEM>>>(bqkv);
    // 2) flash attention
    attn_mma_kernel<<<dim3(SS / 128, BB * HH), 256, ATTN_SMEM>>>();
    // 3) output projection
    out_mma_kernel<<<dim3(8, 32), 256, G_SMEM>>>(bout, out);
}